// round 1
// baseline (speedup 1.0000x reference)
#include <cuda_runtime.h>
#include <cuda_bf16.h>

#define V_   50257
#define VPAD 50304          // 393*128
#define BS_  512            // B*S = 8*64
#define D_   512
#define BM 128
#define BN 128
#define BK 16

// Scratch (static device globals; zero-initialized at module load)
__device__ float g_pnT[D_][BS_];          // normalized perturbed, transposed [k][t]  (1 MB)
__device__ float g_inv_enorm[VPAD];       // 1/max(||emb_v||, 1e-8)
__device__ float g_sim_scratch[(size_t)BS_ * V_];  // used only if sim is not part of d_out

// ---------------- packed f32x2 helpers ----------------
__device__ __forceinline__ unsigned long long pack2(float x) {
    unsigned long long r;
    asm("mov.b64 %0, {%1, %1};" : "=l"(r) : "f"(x));
    return r;
}
__device__ __forceinline__ float2 unpack2(unsigned long long x) {
    float2 f;
    asm("mov.b64 {%0, %1}, %2;" : "=f"(f.x), "=f"(f.y) : "l"(x));
    return f;
}
#define FMA2(d, a, b) \
    asm("fma.rn.f32x2 %0, %1, %2, %0;" : "+l"(d) : "l"(a), "l"(b))

// ---------------- kernel 1: perturb + normalize + transpose ----------------
__global__ void prep_kernel(const int* __restrict__ utt,
                            const float* __restrict__ emb,
                            const float* __restrict__ grad) {
    const int t = blockIdx.x;            // token 0..511
    const int tid = threadIdx.x;         // 128 threads
    const int token = utt[t];
    const float* e = emb + (long long)token * D_;
    const float* g = grad + (long long)t * D_;

    float p[4];
    float ss = 0.f;
#pragma unroll
    for (int j = 0; j < 4; j++) {
        int k = tid + j * 128;
        float gv = g[k];
        float s = (gv > 0.f) ? 1.f : ((gv < 0.f) ? -1.f : 0.f);
        p[j] = e[k] + 0.4f * s;
        ss += p[j] * p[j];
    }
    // block reduce ss (128 threads)
#pragma unroll
    for (int off = 16; off; off >>= 1)
        ss += __shfl_xor_sync(0xffffffffu, ss, off);
    __shared__ float wsum[4];
    if ((tid & 31) == 0) wsum[tid >> 5] = ss;
    __syncthreads();
    float tot = wsum[0] + wsum[1] + wsum[2] + wsum[3];
    float inv = 1.f / fmaxf(sqrtf(tot), 1e-8f);
#pragma unroll
    for (int j = 0; j < 4; j++) {
        int k = tid + j * 128;
        g_pnT[k][t] = p[j] * inv;
    }
}

// ---------------- kernel 2: embedding-row inverse norms ----------------
__global__ void enorm_kernel(const float* __restrict__ emb) {
    const int row = blockIdx.x * 8 + (threadIdx.x >> 5);
    const int lane = threadIdx.x & 31;
    if (row >= V_) return;
    const float4* p = (const float4*)(emb + (long long)row * D_);
    float ss = 0.f;
#pragma unroll
    for (int j = 0; j < 4; j++) {
        float4 v = p[lane + j * 32];
        ss += v.x * v.x + v.y * v.y + v.z * v.z + v.w * v.w;
    }
#pragma unroll
    for (int off = 16; off; off >>= 1)
        ss += __shfl_xor_sync(0xffffffffu, ss, off);
    if (lane == 0)
        g_inv_enorm[row] = 1.f / fmaxf(sqrtf(ss), 1e-8f);
}

// ---------------- kernel 3: sim GEMM (M=V rows of emb, N=512 tokens, K=512) ----
// C[v][t] = dot(emb[v], pn[t]) * inv_enorm[v]; written as sim[t*V + v]
__global__ void __launch_bounds__(256) gemm_kernel(const float* __restrict__ emb,
                                                   float* __restrict__ simout) {
    __shared__ float As[BK][BM];   // emb tile, transposed: As[k][v]
    __shared__ float Bs[BK][BN];   // pnT tile: Bs[k][t]
    __shared__ float Cs[32][BM];   // staging for coalesced stores

    const int vblk = blockIdx.x * BM;
    const int tblk = blockIdx.y * BN;
    const int tid  = threadIdx.x;
    const int v0 = (tid & 15) * 8;     // micro-tile v origin (fast across threads)
    const int t0 = (tid >> 4) * 8;     // micro-tile t origin

    unsigned long long c2[8][4];       // 8 v  x  4 t-pairs, packed f32x2
#pragma unroll
    for (int i = 0; i < 8; i++)
#pragma unroll
        for (int j = 0; j < 4; j++) c2[i][j] = 0ull;

    for (int kb = 0; kb < D_; kb += BK) {
        // A tile: 128 v-rows x 16 k.  512 float4 loads, 2 per thread.
#pragma unroll
        for (int l = 0; l < 2; l++) {
            int idx = tid + l * 256;
            int v  = idx >> 2;
            int k4 = (idx & 3) * 4;
            int gv = vblk + v;
            float4 val = (gv < V_)
                ? *(const float4*)(emb + (long long)gv * D_ + kb + k4)
                : make_float4(0.f, 0.f, 0.f, 0.f);
            As[k4 + 0][v] = val.x; As[k4 + 1][v] = val.y;
            As[k4 + 2][v] = val.z; As[k4 + 3][v] = val.w;
        }
        // B tile: 16 k x 128 t, contiguous in t.
#pragma unroll
        for (int l = 0; l < 2; l++) {
            int idx = tid + l * 256;
            int k  = idx >> 5;
            int t4 = (idx & 31) * 4;
            *(float4*)(&Bs[k][t4]) = *(const float4*)(&g_pnT[kb + k][tblk + t4]);
        }
        __syncthreads();
#pragma unroll
        for (int kk = 0; kk < BK; kk++) {
            float a[8];
            *(float4*)&a[0] = *(const float4*)&As[kk][v0];
            *(float4*)&a[4] = *(const float4*)&As[kk][v0 + 4];
            unsigned long long b2[4];
            const unsigned long long* bp = (const unsigned long long*)&Bs[kk][t0];
#pragma unroll
            for (int j = 0; j < 4; j++) b2[j] = bp[j];
#pragma unroll
            for (int i = 0; i < 8; i++) {
                unsigned long long a2 = pack2(a[i]);
#pragma unroll
                for (int j = 0; j < 4; j++) FMA2(c2[i][j], a2, b2[j]);
            }
        }
        __syncthreads();
    }

    // epilogue: scale by inv_enorm[v], stage through smem 32 t-rows at a time
    float inve[8];
#pragma unroll
    for (int i = 0; i < 8; i++) inve[i] = g_inv_enorm[vblk + v0 + i];

    const int myphase = t0 >> 5;
    for (int p = 0; p < 4; p++) {
        __syncthreads();
        if (myphase == p) {
#pragma unroll
            for (int j = 0; j < 4; j++) {
                float2 f0 = unpack2(c2[0][j]); // unpack per (i,j); loop i below
#pragma unroll
                for (int h = 0; h < 2; h++) {
                    int tl = (t0 & 31) + 2 * j + h;
#pragma unroll
                    for (int i = 0; i < 8; i++) {
                        float2 f = unpack2(c2[i][j]);
                        float val = (h ? f.y : f.x) * inve[i];
                        Cs[tl][v0 + i] = val;
                    }
                }
                (void)f0;
            }
        }
        __syncthreads();
        // copy 32 rows x 128 floats, coalesced
        for (int x = tid; x < 32 * BM; x += 256) {
            int tl = x >> 7;
            int vv = x & 127;
            int gv = vblk + vv;
            int gt = tblk + p * 32 + tl;
            if (gv < V_)
                simout[(long long)gt * V_ + gv] = Cs[tl][vv];
        }
    }
}

// ---------------- kernel 4: tie-aware argmax per token ----------------
__global__ void argmax_kernel(const float* __restrict__ sim,
                              const float* __restrict__ noise,
                              void* __restrict__ out, int write_float) {
    const int t = blockIdx.x;
    const int tid = threadIdx.x;    // 256
    const float* srow = sim + (long long)t * V_;
    const float* nrow = noise + (long long)t * V_;

    float bs = -2.f, bn = -2.f;
    int bi = 0x7fffffff;
    for (int v = tid; v < V_; v += 256) {
        float s = srow[v];
        float n = nrow[v];
        if (s > bs || (s == bs && (n > bn || (n == bn && v < bi)))) {
            bs = s; bn = n; bi = v;
        }
    }
    __shared__ float ss[256], sn[256];
    __shared__ int   si[256];
    ss[tid] = bs; sn[tid] = bn; si[tid] = bi;
    for (int off = 128; off; off >>= 1) {
        __syncthreads();
        if (tid < off) {
            float s2 = ss[tid + off], n2 = sn[tid + off];
            int   i2 = si[tid + off];
            float s1 = ss[tid], n1 = sn[tid];
            int   i1 = si[tid];
            bool take = (s2 > s1) ||
                        (s2 == s1 && (n2 > n1 || (n2 == n1 && i2 < i1)));
            if (take) { ss[tid] = s2; sn[tid] = n2; si[tid] = i2; }
        }
    }
    __syncthreads();
    if (tid == 0) {
        if (write_float) ((float*)out)[t] = (float)si[0];
        else             ((int*)out)[t]   = si[0];
    }
}

// ---------------- launcher ----------------
extern "C" void kernel_launch(void* const* d_in, const int* in_sizes, int n_in,
                              void* d_out, int out_size) {
    const int*   utt   = (const int*)d_in[0];
    const float* emb   = (const float*)d_in[1];
    const float* grad  = (const float*)d_in[2];
    const float* noise = (const float*)d_in[3];

    prep_kernel<<<BS_, 128>>>(utt, emb, grad);
    enorm_kernel<<<(V_ + 7) / 8, 256>>>(emb);

    const long long SIMN = (long long)BS_ * V_;
    float* simptr;
    float* simscr;
    cudaGetSymbolAddress((void**)&simscr, g_sim_scratch);

    if ((long long)out_size == SIMN + BS_)      simptr = (float*)d_out + BS_;
    else if ((long long)out_size == SIMN)       simptr = (float*)d_out;
    else                                        simptr = simscr;

    dim3 grid((V_ + BM - 1) / BM, BS_ / BN);
    gemm_kernel<<<grid, 256>>>(emb, simptr);

    if ((long long)out_size == SIMN + BS_)
        argmax_kernel<<<BS_, 256>>>(simptr, noise, d_out, 1);
    else if (out_size == BS_)
        argmax_kernel<<<BS_, 256>>>(simptr, noise, d_out, 0);
}

// round 2
// speedup vs baseline: 1.0039x; 1.0039x over previous
#include <cuda_runtime.h>
#include <cuda_bf16.h>

#define V_   50257
#define VPAD 50304          // 393*128
#define BS_  512            // B*S = 8*64
#define D_   512
#define BM 128
#define BN 128
#define BK 16

// Scratch (static device globals; zero-initialized at module load)
__device__ float g_pnT[D_][BS_];          // normalized perturbed, transposed [k][t]  (1 MB)
__device__ float g_inv_enorm[VPAD];       // 1/max(||emb_v||, 1e-8)
__device__ float g_sim_scratch[(size_t)BS_ * V_];  // used only if sim is not part of d_out

// ---------------- packed f32x2 helpers ----------------
__device__ __forceinline__ unsigned long long pack2(float x) {
    unsigned long long r;
    asm("mov.b64 %0, {%1, %1};" : "=l"(r) : "f"(x));
    return r;
}
__device__ __forceinline__ float2 unpack2(unsigned long long x) {
    float2 f;
    asm("mov.b64 {%0, %1}, %2;" : "=f"(f.x), "=f"(f.y) : "l"(x));
    return f;
}
#define FMA2(d, a, b) \
    asm("fma.rn.f32x2 %0, %1, %2, %0;" : "+l"(d) : "l"(a), "l"(b))

// ---------------- kernel 1: perturb + normalize + transpose ----------------
__global__ void prep_kernel(const int* __restrict__ utt,
                            const float* __restrict__ emb,
                            const float* __restrict__ grad) {
    const int t = blockIdx.x;            // token 0..511
    const int tid = threadIdx.x;         // 128 threads
    const int token = utt[t];
    const float* e = emb + (long long)token * D_;
    const float* g = grad + (long long)t * D_;

    float p[4];
    float ss = 0.f;
#pragma unroll
    for (int j = 0; j < 4; j++) {
        int k = tid + j * 128;
        float gv = g[k];
        float s = (gv > 0.f) ? 1.f : ((gv < 0.f) ? -1.f : 0.f);
        p[j] = e[k] + 0.4f * s;
        ss += p[j] * p[j];
    }
    // block reduce ss (128 threads)
#pragma unroll
    for (int off = 16; off; off >>= 1)
        ss += __shfl_xor_sync(0xffffffffu, ss, off);
    __shared__ float wsum[4];
    if ((tid & 31) == 0) wsum[tid >> 5] = ss;
    __syncthreads();
    float tot = wsum[0] + wsum[1] + wsum[2] + wsum[3];
    float inv = 1.f / fmaxf(sqrtf(tot), 1e-8f);
#pragma unroll
    for (int j = 0; j < 4; j++) {
        int k = tid + j * 128;
        g_pnT[k][t] = p[j] * inv;
    }
}

// ---------------- kernel 2: embedding-row inverse norms ----------------
__global__ void enorm_kernel(const float* __restrict__ emb) {
    const int row = blockIdx.x * 8 + (threadIdx.x >> 5);
    const int lane = threadIdx.x & 31;
    if (row >= V_) return;
    const float4* p = (const float4*)(emb + (long long)row * D_);
    float ss = 0.f;
#pragma unroll
    for (int j = 0; j < 4; j++) {
        float4 v = p[lane + j * 32];
        ss += v.x * v.x + v.y * v.y + v.z * v.z + v.w * v.w;
    }
#pragma unroll
    for (int off = 16; off; off >>= 1)
        ss += __shfl_xor_sync(0xffffffffu, ss, off);
    if (lane == 0)
        g_inv_enorm[row] = 1.f / fmaxf(sqrtf(ss), 1e-8f);
}

// ---------------- kernel 3: sim GEMM (M=V rows of emb, N=512 tokens, K=512) ----
// C[v][t] = dot(emb[v], pn[t]) * inv_enorm[v]; written as sim[t*V + v]
__global__ void __launch_bounds__(256) gemm_kernel(const float* __restrict__ emb,
                                                   float* __restrict__ simout) {
    __shared__ float As[BK][BM];   // emb tile, transposed: As[k][v]
    __shared__ float Bs[BK][BN];   // pnT tile: Bs[k][t]
    __shared__ float Cs[32][BM];   // staging for coalesced stores

    const int vblk = blockIdx.x * BM;
    const int tblk = blockIdx.y * BN;
    const int tid  = threadIdx.x;
    const int v0 = (tid & 15) * 8;     // micro-tile v origin (fast across threads)
    const int t0 = (tid >> 4) * 8;     // micro-tile t origin

    unsigned long long c2[8][4];       // 8 v  x  4 t-pairs, packed f32x2
#pragma unroll
    for (int i = 0; i < 8; i++)
#pragma unroll
        for (int j = 0; j < 4; j++) c2[i][j] = 0ull;

    for (int kb = 0; kb < D_; kb += BK) {
        // A tile: 128 v-rows x 16 k.  512 float4 loads, 2 per thread.
#pragma unroll
        for (int l = 0; l < 2; l++) {
            int idx = tid + l * 256;
            int v  = idx >> 2;
            int k4 = (idx & 3) * 4;
            int gv = vblk + v;
            float4 val = (gv < V_)
                ? *(const float4*)(emb + (long long)gv * D_ + kb + k4)
                : make_float4(0.f, 0.f, 0.f, 0.f);
            As[k4 + 0][v] = val.x; As[k4 + 1][v] = val.y;
            As[k4 + 2][v] = val.z; As[k4 + 3][v] = val.w;
        }
        // B tile: 16 k x 128 t, contiguous in t.
#pragma unroll
        for (int l = 0; l < 2; l++) {
            int idx = tid + l * 256;
            int k  = idx >> 5;
            int t4 = (idx & 31) * 4;
            *(float4*)(&Bs[k][t4]) = *(const float4*)(&g_pnT[kb + k][tblk + t4]);
        }
        __syncthreads();
#pragma unroll
        for (int kk = 0; kk < BK; kk++) {
            float a[8];
            *(float4*)&a[0] = *(const float4*)&As[kk][v0];
            *(float4*)&a[4] = *(const float4*)&As[kk][v0 + 4];
            unsigned long long b2[4];
            const unsigned long long* bp = (const unsigned long long*)&Bs[kk][t0];
#pragma unroll
            for (int j = 0; j < 4; j++) b2[j] = bp[j];
#pragma unroll
            for (int i = 0; i < 8; i++) {
                unsigned long long a2 = pack2(a[i]);
#pragma unroll
                for (int j = 0; j < 4; j++) FMA2(c2[i][j], a2, b2[j]);
            }
        }
        __syncthreads();
    }

    // epilogue: scale by inv_enorm[v], stage through smem 32 t-rows at a time
    float inve[8];
#pragma unroll
    for (int i = 0; i < 8; i++) inve[i] = g_inv_enorm[vblk + v0 + i];

    const int myphase = t0 >> 5;
    for (int p = 0; p < 4; p++) {
        __syncthreads();
        if (myphase == p) {
#pragma unroll
            for (int j = 0; j < 4; j++) {
                float2 f0 = unpack2(c2[0][j]); // unpack per (i,j); loop i below
#pragma unroll
                for (int h = 0; h < 2; h++) {
                    int tl = (t0 & 31) + 2 * j + h;
#pragma unroll
                    for (int i = 0; i < 8; i++) {
                        float2 f = unpack2(c2[i][j]);
                        float val = (h ? f.y : f.x) * inve[i];
                        Cs[tl][v0 + i] = val;
                    }
                }
                (void)f0;
            }
        }
        __syncthreads();
        // copy 32 rows x 128 floats, coalesced
        for (int x = tid; x < 32 * BM; x += 256) {
            int tl = x >> 7;
            int vv = x & 127;
            int gv = vblk + vv;
            int gt = tblk + p * 32 + tl;
            if (gv < V_)
                simout[(long long)gt * V_ + gv] = Cs[tl][vv];
        }
    }
}

// ---------------- kernel 4: tie-aware argmax per token ----------------
__global__ void argmax_kernel(const float* __restrict__ sim,
                              const float* __restrict__ noise,
                              void* __restrict__ out, int write_float) {
    const int t = blockIdx.x;
    const int tid = threadIdx.x;    // 256
    const float* srow = sim + (long long)t * V_;
    const float* nrow = noise + (long long)t * V_;

    float bs = -2.f, bn = -2.f;
    int bi = 0x7fffffff;
    for (int v = tid; v < V_; v += 256) {
        float s = srow[v];
        float n = nrow[v];
        if (s > bs || (s == bs && (n > bn || (n == bn && v < bi)))) {
            bs = s; bn = n; bi = v;
        }
    }
    __shared__ float ss[256], sn[256];
    __shared__ int   si[256];
    ss[tid] = bs; sn[tid] = bn; si[tid] = bi;
    for (int off = 128; off; off >>= 1) {
        __syncthreads();
        if (tid < off) {
            float s2 = ss[tid + off], n2 = sn[tid + off];
            int   i2 = si[tid + off];
            float s1 = ss[tid], n1 = sn[tid];
            int   i1 = si[tid];
            bool take = (s2 > s1) ||
                        (s2 == s1 && (n2 > n1 || (n2 == n1 && i2 < i1)));
            if (take) { ss[tid] = s2; sn[tid] = n2; si[tid] = i2; }
        }
    }
    __syncthreads();
    if (tid == 0) {
        if (write_float) ((float*)out)[t] = (float)si[0];
        else             ((int*)out)[t]   = si[0];
    }
}

// ---------------- launcher ----------------
extern "C" void kernel_launch(void* const* d_in, const int* in_sizes, int n_in,
                              void* d_out, int out_size) {
    const int*   utt   = (const int*)d_in[0];
    const float* emb   = (const float*)d_in[1];
    const float* grad  = (const float*)d_in[2];
    const float* noise = (const float*)d_in[3];

    prep_kernel<<<BS_, 128>>>(utt, emb, grad);
    enorm_kernel<<<(V_ + 7) / 8, 256>>>(emb);

    const long long SIMN = (long long)BS_ * V_;
    float* simptr;
    float* simscr;
    cudaGetSymbolAddress((void**)&simscr, g_sim_scratch);

    if ((long long)out_size == SIMN + BS_)      simptr = (float*)d_out + BS_;
    else if ((long long)out_size == SIMN)       simptr = (float*)d_out;
    else                                        simptr = simscr;

    dim3 grid((V_ + BM - 1) / BM, BS_ / BN);
    gemm_kernel<<<grid, 256>>>(emb, simptr);

    if ((long long)out_size == SIMN + BS_)
        argmax_kernel<<<BS_, 256>>>(simptr, noise, d_out, 1);
    else if (out_size == BS_)
        argmax_kernel<<<BS_, 256>>>(simptr, noise, d_out, 0);
}

// round 4
// speedup vs baseline: 1.9923x; 1.9847x over previous
#include <cuda_runtime.h>
#include <cuda_bf16.h>
#include <cstdint>

#define V_    50257
#define VPAD  50304
#define BS_   512
#define D_    512
#define BM    128
#define BN    256
#define BKF   64
#define NCH   (D_/BKF)

__device__ uint2 g_pnh2[BS_*D_/4];      // pn hi bf16 pairs [t][k/4]
__device__ uint2 g_pnl2[BS_*D_/4];      // pn lo bf16 pairs
__device__ float g_inv_enorm[VPAD];
__device__ float g_sim_scratch[(size_t)BS_*V_];

#define SW128(x) ((x) ^ (((x) >> 3) & 0x70))

__device__ __forceinline__ uint32_t smem_u32(const void* p){
    uint32_t a;
    asm("{ .reg .u64 t; cvta.to.shared.u64 t, %1; cvt.u32.u64 %0, t; }" : "=r"(a) : "l"(p));
    return a;
}
__device__ __forceinline__ uint32_t bf16x2_of(float lo, float hi){
    uint32_t r;
    asm("cvt.rn.bf16x2.f32 %0, %1, %2;" : "=r"(r) : "f"(hi), "f"(lo));
    return r;
}
__device__ __forceinline__ void ldsm4(uint32_t* r, uint32_t addr){
    asm volatile("ldmatrix.sync.aligned.m8n8.x4.shared.b16 {%0,%1,%2,%3}, [%4];"
        : "=r"(r[0]), "=r"(r[1]), "=r"(r[2]), "=r"(r[3]) : "r"(addr));
}
#define MMA16816(c, a, b0v, b1v) \
    asm volatile("mma.sync.aligned.m16n8k16.row.col.f32.bf16.bf16.f32 " \
        "{%0,%1,%2,%3}, {%4,%5,%6,%7}, {%8,%9}, {%0,%1,%2,%3};" \
        : "+f"((c)[0]), "+f"((c)[1]), "+f"((c)[2]), "+f"((c)[3]) \
        : "r"((a)[0]), "r"((a)[1]), "r"((a)[2]), "r"((a)[3]), "r"(b0v), "r"(b1v))

// ---------------- kernel 1: perturb + normalize + bf16 split ----------------
__global__ void prep_kernel(const int* __restrict__ utt, const float* __restrict__ emb,
                            const float* __restrict__ grad) {
    const int t = blockIdx.x, tid = threadIdx.x;  // 128 threads
    const int token = utt[t];
    float4 e = *(const float4*)(emb + (size_t)token * D_ + tid * 4);
    float4 g = *(const float4*)(grad + (size_t)t * D_ + tid * 4);
    float p0 = e.x + 0.4f * ((g.x > 0.f) ? 1.f : ((g.x < 0.f) ? -1.f : 0.f));
    float p1 = e.y + 0.4f * ((g.y > 0.f) ? 1.f : ((g.y < 0.f) ? -1.f : 0.f));
    float p2 = e.z + 0.4f * ((g.z > 0.f) ? 1.f : ((g.z < 0.f) ? -1.f : 0.f));
    float p3 = e.w + 0.4f * ((g.w > 0.f) ? 1.f : ((g.w < 0.f) ? -1.f : 0.f));
    float ss = p0*p0 + p1*p1 + p2*p2 + p3*p3;
#pragma unroll
    for (int off = 16; off; off >>= 1) ss += __shfl_xor_sync(0xffffffffu, ss, off);
    __shared__ float wsum[4];
    if ((tid & 31) == 0) wsum[tid >> 5] = ss;
    __syncthreads();
    float inv = 1.f / fmaxf(sqrtf(wsum[0] + wsum[1] + wsum[2] + wsum[3]), 1e-8f);
    p0 *= inv; p1 *= inv; p2 *= inv; p3 *= inv;
    uint32_t h01 = bf16x2_of(p0, p1), h23 = bf16x2_of(p2, p3);
    float l0 = p0 - __uint_as_float(h01 << 16);
    float l1 = p1 - __uint_as_float(h01 & 0xFFFF0000u);
    float l2 = p2 - __uint_as_float(h23 << 16);
    float l3 = p3 - __uint_as_float(h23 & 0xFFFF0000u);
    g_pnh2[t * 128 + tid] = make_uint2(h01, h23);
    g_pnl2[t * 128 + tid] = make_uint2(bf16x2_of(l0, l1), bf16x2_of(l2, l3));
}

// ---------------- kernel 2: embedding inverse norms ----------------
__global__ void enorm_kernel(const float* __restrict__ emb) {
    const int row = blockIdx.x * 8 + (threadIdx.x >> 5);
    const int lane = threadIdx.x & 31;
    if (row >= V_) return;
    const float4* p = (const float4*)(emb + (size_t)row * D_);
    float ss = 0.f;
#pragma unroll
    for (int j = 0; j < 4; j++) {
        float4 v = p[lane + j * 32];
        ss += v.x*v.x + v.y*v.y + v.z*v.z + v.w*v.w;
    }
#pragma unroll
    for (int off = 16; off; off >>= 1) ss += __shfl_xor_sync(0xffffffffu, ss, off);
    if (lane == 0) g_inv_enorm[row] = 1.f / fmaxf(sqrtf(ss), 1e-8f);
}

// ---------------- kernel 3: HMMA bf16x3 GEMM  C[v][t] ----------------
// A = emb [BM x 64] (hi/lo), B = pn [BN x 64] (hi/lo), K chunks of 64.
__global__ void __launch_bounds__(512) gemm_kernel(const float* __restrict__ emb,
                                                   float* __restrict__ simout) {
    extern __shared__ char smem[];
    const uint32_t sb = smem_u32(smem);
    const int tid = threadIdx.x;
    const int wid = tid >> 5, lane = tid & 31;
    const int tblk = blockIdx.x * BN;
    const int vblk = blockIdx.y * BM;

    const uint32_t AH = 0, AL = 16384, BH = 32768, BL = 98304 - 32768; // BL=65536

    float acc[2][8][4];
#pragma unroll
    for (int i = 0; i < 2; i++)
#pragma unroll
        for (int j = 0; j < 8; j++)
#pragma unroll
            for (int q = 0; q < 4; q++) acc[i][j][q] = 0.f;

    const int mw = (wid >> 2) * 32;
    const int nw = (wid & 3) * 64;
    const int a_row = (lane & 7) + ((lane >> 3) & 1) * 8;
    const int a_kb  = ((lane >> 4) & 1) * 16;
    const int b_row = (lane & 7) + ((lane >> 4) & 1) * 8;
    const int b_kb  = ((lane >> 3) & 1) * 16;

    for (int c = 0; c < NCH; c++) {
        if (c) __syncthreads();          // prior compute done before overwrite
        const int kb = c * BKF;
        // ---- A: emb fp32 -> bf16 hi/lo ----
#pragma unroll
        for (int l = 0; l < 4; l++) {
            int idx = tid + 512 * l;
            int row = idx >> 4, k4 = idx & 15;
            int gv = vblk + row;
            float4 x = make_float4(0.f, 0.f, 0.f, 0.f);
            if (gv < V_) x = *(const float4*)(emb + (size_t)gv * D_ + kb + k4 * 4);
            uint32_t h01 = bf16x2_of(x.x, x.y), h23 = bf16x2_of(x.z, x.w);
            float l0 = x.x - __uint_as_float(h01 << 16);
            float l1 = x.y - __uint_as_float(h01 & 0xFFFF0000u);
            float l2 = x.z - __uint_as_float(h23 << 16);
            float l3 = x.w - __uint_as_float(h23 & 0xFFFF0000u);
            uint32_t l01 = bf16x2_of(l0, l1), l23 = bf16x2_of(l2, l3);
            uint32_t off = SW128((uint32_t)(row * 128 + k4 * 8));
            asm volatile("st.shared.v2.b32 [%0], {%1,%2};" :: "r"(sb + AH + off), "r"(h01), "r"(h23));
            asm volatile("st.shared.v2.b32 [%0], {%1,%2};" :: "r"(sb + AL + off), "r"(l01), "r"(l23));
        }
        // ---- B: pre-split pn ----
#pragma unroll
        for (int l = 0; l < 8; l++) {
            int idx = tid + 512 * l;
            int row = idx >> 4, k4 = idx & 15;
            int src = (tblk + row) * 128 + c * 16 + k4;
            uint2 h = g_pnh2[src], lo = g_pnl2[src];
            uint32_t off = SW128((uint32_t)(row * 128 + k4 * 8));
            asm volatile("st.shared.v2.b32 [%0], {%1,%2};" :: "r"(sb + BH + off), "r"(h.x), "r"(h.y));
            asm volatile("st.shared.v2.b32 [%0], {%1,%2};" :: "r"(sb + BL + off), "r"(lo.x), "r"(lo.y));
        }
        __syncthreads();
        // ---- compute 4 k16-steps x 3 terms ----
#pragma unroll
        for (int s = 0; s < 4; s++) {
            uint32_t a[8], b[16];
            const uint32_t akoff = (uint32_t)(s * 32 + a_kb);
            const uint32_t bkoff = (uint32_t)(s * 32 + b_kb);
#pragma unroll
            for (int i = 0; i < 2; i++)
                ldsm4(&a[i*4], sb + AH + SW128((uint32_t)((mw + i*16 + a_row) * 128) + akoff));
#pragma unroll
            for (int j2 = 0; j2 < 4; j2++)
                ldsm4(&b[j2*4], sb + BH + SW128((uint32_t)((nw + j2*16 + b_row) * 128) + bkoff));
#pragma unroll
            for (int i = 0; i < 2; i++)
#pragma unroll
                for (int j = 0; j < 8; j++)
                    MMA16816(acc[i][j], &a[i*4], b[(j>>1)*4 + (j&1)*2], b[(j>>1)*4 + (j&1)*2 + 1]);
            // hi x lo
#pragma unroll
            for (int j2 = 0; j2 < 4; j2++)
                ldsm4(&b[j2*4], sb + BL + SW128((uint32_t)((nw + j2*16 + b_row) * 128) + bkoff));
#pragma unroll
            for (int i = 0; i < 2; i++)
#pragma unroll
                for (int j = 0; j < 8; j++)
                    MMA16816(acc[i][j], &a[i*4], b[(j>>1)*4 + (j&1)*2], b[(j>>1)*4 + (j&1)*2 + 1]);
            // lo x hi
#pragma unroll
            for (int i = 0; i < 2; i++)
                ldsm4(&a[i*4], sb + AL + SW128((uint32_t)((mw + i*16 + a_row) * 128) + akoff));
#pragma unroll
            for (int j2 = 0; j2 < 4; j2++)
                ldsm4(&b[j2*4], sb + BH + SW128((uint32_t)((nw + j2*16 + b_row) * 128) + bkoff));
#pragma unroll
            for (int i = 0; i < 2; i++)
#pragma unroll
                for (int j = 0; j < 8; j++)
                    MMA16816(acc[i][j], &a[i*4], b[(j>>1)*4 + (j&1)*2], b[(j>>1)*4 + (j&1)*2 + 1]);
        }
    }

    // ---- epilogue: transpose-stage 64 tokens at a time, scale, store ----
    float* cs = (float*)smem;          // [64][132] floats = 33792 B
    for (int p = 0; p < 4; p++) {
        __syncthreads();
        if (nw == p * 64) {
#pragma unroll
            for (int i = 0; i < 2; i++)
#pragma unroll
                for (int j = 0; j < 8; j++) {
                    int v0 = mw + i * 16 + (lane >> 2);
                    int tl = j * 8 + (lane & 3) * 2;
                    cs[ tl      * 132 + v0    ] = acc[i][j][0];
                    cs[(tl + 1) * 132 + v0    ] = acc[i][j][1];
                    cs[ tl      * 132 + v0 + 8] = acc[i][j][2];
                    cs[(tl + 1) * 132 + v0 + 8] = acc[i][j][3];
                }
        }
        __syncthreads();
        int v4 = (tid & 31) * 4;
#pragma unroll
        for (int it = 0; it < 4; it++) {
            int tl = (tid >> 5) + it * 16;
            float4 val = *(float4*)(cs + tl * 132 + v4);
            float4 e4  = *(const float4*)(g_inv_enorm + vblk + v4);
            int gt = tblk + p * 64 + tl;
            int gv = vblk + v4;
            float* dst = simout + (size_t)gt * V_ + gv;
            if (gv + 3 < V_) {
                dst[0] = val.x * e4.x; dst[1] = val.y * e4.y;
                dst[2] = val.z * e4.z; dst[3] = val.w * e4.w;
            } else {
                if (gv     < V_) dst[0] = val.x * e4.x;
                if (gv + 1 < V_) dst[1] = val.y * e4.y;
                if (gv + 2 < V_) dst[2] = val.z * e4.z;
                if (gv + 3 < V_) dst[3] = val.w * e4.w;
            }
        }
    }
}

// ---------------- kernel 4: tie-aware argmax, lazy noise ----------------
__global__ void argmax_kernel(const float* __restrict__ sim, const float* __restrict__ noise,
                              void* __restrict__ out, int write_float) {
    const int t = blockIdx.x, tid = threadIdx.x;   // 256 threads
    const float* srow = sim + (size_t)t * V_;
    const float* nrow = noise + (size_t)t * V_;

    float bs = -2.f; int bi = 0;
    uintptr_t pa = (uintptr_t)srow;
    int a0 = ((16 - (int)(pa & 15)) & 15) >> 2;
    if (tid < a0) { bs = srow[tid]; bi = tid; }

    const int nv4 = (V_ - a0) >> 2;
    const float4* s4p = (const float4*)(srow + a0);
    for (int i = tid; i < nv4; i += 256) {
        float4 s4 = s4p[i];
        float m = fmaxf(fmaxf(s4.x, s4.y), fmaxf(s4.z, s4.w));
        if (m < bs) continue;
        float e[4] = {s4.x, s4.y, s4.z, s4.w};
        int vb = a0 + i * 4;
#pragma unroll
        for (int u = 0; u < 4; u++) {
            float s = e[u]; int v = vb + u;
            if (s > bs) { bs = s; bi = v; }
            else if (s == bs) {
                float ncur = nrow[bi], nnew = nrow[v];
                if (nnew > ncur || (nnew == ncur && v < bi)) bi = v;
            }
        }
    }
    for (int v = a0 + nv4 * 4 + tid; v < V_; v += 256) {
        float s = srow[v];
        if (s > bs) { bs = s; bi = v; }
        else if (s == bs) {
            float ncur = nrow[bi], nnew = nrow[v];
            if (nnew > ncur || (nnew == ncur && v < bi)) bi = v;
        }
    }
    float bn = (bs > -2.f) ? nrow[bi] : -2.f;

    __shared__ float ss[256], sn[256];
    __shared__ int   si[256];
    ss[tid] = bs; sn[tid] = bn; si[tid] = bi;
    for (int off = 128; off; off >>= 1) {
        __syncthreads();
        if (tid < off) {
            float s2 = ss[tid + off], n2 = sn[tid + off];
            int   i2 = si[tid + off];
            bool take = (s2 > ss[tid]) ||
                        (s2 == ss[tid] && (n2 > sn[tid] || (n2 == sn[tid] && i2 < si[tid])));
            if (take) { ss[tid] = s2; sn[tid] = n2; si[tid] = i2; }
        }
    }
    __syncthreads();
    if (tid == 0) {
        if (write_float) ((float*)out)[t] = (float)si[0];
        else             ((int*)out)[t]   = si[0];
    }
}

// ---------------- launcher ----------------
extern "C" void kernel_launch(void* const* d_in, const int* in_sizes, int n_in,
                              void* d_out, int out_size) {
    const int*   utt   = (const int*)d_in[0];
    const float* emb   = (const float*)d_in[1];
    const float* grad  = (const float*)d_in[2];
    const float* noise = (const float*)d_in[3];

    prep_kernel<<<BS_, 128>>>(utt, emb, grad);
    enorm_kernel<<<(V_ + 7) / 8, 256>>>(emb);

    const long long SIMN = (long long)BS_ * V_;
    float* simptr;
    float* simscr;
    cudaGetSymbolAddress((void**)&simscr, g_sim_scratch);
    if ((long long)out_size == SIMN + BS_)      simptr = (float*)d_out + BS_;
    else if ((long long)out_size == SIMN)       simptr = (float*)d_out;
    else                                        simptr = simscr;

    cudaFuncSetAttribute(gemm_kernel, cudaFuncAttributeMaxDynamicSharedMemorySize, 98304);
    dim3 grid(BS_ / BN, VPAD / BM);
    gemm_kernel<<<grid, 512, 98304>>>(emb, simptr);

    if ((long long)out_size == SIMN + BS_)
        argmax_kernel<<<BS_, 256>>>(simptr, noise, d_out, 1);
    else if (out_size == BS_)
        argmax_kernel<<<BS_, 256>>>(simptr, noise, d_out, 0);
}

// round 6
// speedup vs baseline: 2.4245x; 1.2169x over previous
#include <cuda_runtime.h>
#include <cuda_bf16.h>
#include <cstdint>

#define V_    50257
#define VPAD  50304
#define NVB   393          // vocab blocks
#define BS_   512
#define D_    512
#define BM    128
#define BN    128
#define BKF   64
#define NCH   (D_/BKF)

__device__ __align__(16) uint2 g_pnh2[BS_*D_/4];   // pn hi bf16 pairs [t][k/4]
__device__ __align__(16) uint2 g_pnl2[BS_*D_/4];   // pn lo bf16 pairs
__device__ float g_inv_enorm[VPAD];
__device__ float g_sim_scratch[(size_t)BS_*V_];
__device__ float g_part_s[BS_*NVB];
__device__ int   g_part_i[BS_*NVB];

#define SW128(x) ((x) ^ (((x) >> 3) & 0x70))

__device__ __forceinline__ uint32_t smem_u32(const void* p){
    uint32_t a;
    asm("{ .reg .u64 t; cvta.to.shared.u64 t, %1; cvt.u32.u64 %0, t; }" : "=r"(a) : "l"(p));
    return a;
}
__device__ __forceinline__ uint32_t bf16x2_of(float lo, float hi){
    uint32_t r;
    asm("cvt.rn.bf16x2.f32 %0, %1, %2;" : "=r"(r) : "f"(hi), "f"(lo));
    return r;
}
__device__ __forceinline__ void ldsm4(uint32_t* r, uint32_t addr){
    asm volatile("ldmatrix.sync.aligned.m8n8.x4.shared.b16 {%0,%1,%2,%3}, [%4];"
        : "=r"(r[0]), "=r"(r[1]), "=r"(r[2]), "=r"(r[3]) : "r"(addr));
}
#define MMA16816(c, a, b0v, b1v) \
    asm volatile("mma.sync.aligned.m16n8k16.row.col.f32.bf16.bf16.f32 " \
        "{%0,%1,%2,%3}, {%4,%5,%6,%7}, {%8,%9}, {%0,%1,%2,%3};" \
        : "+f"((c)[0]), "+f"((c)[1]), "+f"((c)[2]), "+f"((c)[3]) \
        : "r"((a)[0]), "r"((a)[1]), "r"((a)[2]), "r"((a)[3]), "r"(b0v), "r"(b1v))
#define CPASYNC16(dst, src) \
    asm volatile("cp.async.cg.shared.global [%0], [%1], 16;" :: "r"(dst), "l"(src))
#define CPCOMMIT() asm volatile("cp.async.commit_group;" ::: "memory")
#define CPWAIT0()  asm volatile("cp.async.wait_group 0;" ::: "memory")

// ---------------- kernel 1: perturb + normalize + bf16 split ----------------
__global__ void prep_kernel(const int* __restrict__ utt, const float* __restrict__ emb,
                            const float* __restrict__ grad) {
    const int t = blockIdx.x, tid = threadIdx.x;  // 128 threads
    const int token = utt[t];
    float4 e = *(const float4*)(emb + (size_t)token * D_ + tid * 4);
    float4 g = *(const float4*)(grad + (size_t)t * D_ + tid * 4);
    float p0 = e.x + 0.4f * ((g.x > 0.f) ? 1.f : ((g.x < 0.f) ? -1.f : 0.f));
    float p1 = e.y + 0.4f * ((g.y > 0.f) ? 1.f : ((g.y < 0.f) ? -1.f : 0.f));
    float p2 = e.z + 0.4f * ((g.z > 0.f) ? 1.f : ((g.z < 0.f) ? -1.f : 0.f));
    float p3 = e.w + 0.4f * ((g.w > 0.f) ? 1.f : ((g.w < 0.f) ? -1.f : 0.f));
    float ss = p0*p0 + p1*p1 + p2*p2 + p3*p3;
#pragma unroll
    for (int off = 16; off; off >>= 1) ss += __shfl_xor_sync(0xffffffffu, ss, off);
    __shared__ float wsum[4];
    if ((tid & 31) == 0) wsum[tid >> 5] = ss;
    __syncthreads();
    float inv = 1.f / fmaxf(sqrtf(wsum[0] + wsum[1] + wsum[2] + wsum[3]), 1e-8f);
    p0 *= inv; p1 *= inv; p2 *= inv; p3 *= inv;
    uint32_t h01 = bf16x2_of(p0, p1), h23 = bf16x2_of(p2, p3);
    float l0 = p0 - __uint_as_float(h01 << 16);
    float l1 = p1 - __uint_as_float(h01 & 0xFFFF0000u);
    float l2 = p2 - __uint_as_float(h23 << 16);
    float l3 = p3 - __uint_as_float(h23 & 0xFFFF0000u);
    g_pnh2[t * 128 + tid] = make_uint2(h01, h23);
    g_pnl2[t * 128 + tid] = make_uint2(bf16x2_of(l0, l1), bf16x2_of(l2, l3));
}

// ---------------- kernel 2: embedding inverse norms ----------------
__global__ void enorm_kernel(const float* __restrict__ emb) {
    const int row = blockIdx.x * 8 + (threadIdx.x >> 5);
    const int lane = threadIdx.x & 31;
    if (row >= V_) return;
    const float4* p = (const float4*)(emb + (size_t)row * D_);
    float ss = 0.f;
#pragma unroll
    for (int j = 0; j < 4; j++) {
        float4 v = p[lane + j * 32];
        ss += v.x*v.x + v.y*v.y + v.z*v.z + v.w*v.w;
    }
#pragma unroll
    for (int off = 16; off; off >>= 1) ss += __shfl_xor_sync(0xffffffffu, ss, off);
    if (lane == 0) g_inv_enorm[row] = 1.f / fmaxf(sqrtf(ss), 1e-8f);
}

// ---------------- kernel 3: pipelined HMMA bf16x3 GEMM + fused partial argmax --
__global__ void __launch_bounds__(512) gemm_kernel(const float* __restrict__ emb,
                                                   float* __restrict__ simout,
                                                   const float* __restrict__ noise) {
    extern __shared__ char smem[];
    const uint32_t sb = smem_u32(smem);
    const int tid = threadIdx.x;
    const int wid = tid >> 5, lane = tid & 31;
    const int tblk = blockIdx.x * BN;
    const int vblk = blockIdx.y * BM;

    const uint32_t AH = 0, AL = 16384;

    float acc[2][4][4];
#pragma unroll
    for (int i = 0; i < 2; i++)
#pragma unroll
        for (int j = 0; j < 4; j++)
#pragma unroll
            for (int q = 0; q < 4; q++) acc[i][j][q] = 0.f;

    const int mw = (wid >> 2) * 32;
    const int nw = (wid & 3) * 32;
    const int a_row = (lane & 7) + ((lane >> 3) & 1) * 8;
    const int a_kb  = ((lane >> 4) & 1) * 16;
    const int b_row = (lane & 7) + ((lane >> 4) & 1) * 8;
    const int b_kb  = ((lane >> 3) & 1) * 16;

    const int arow = tid >> 4;
    const int ak4  = tid & 15;

    // ---- preamble: issue B(0), prefetch A(0) ----
    float4 apre[4];
#pragma unroll
    for (int l = 0; l < 4; l++) {
        int row = arow + 32 * l;
        int gv = vblk + row;
        apre[l] = (gv < V_) ? *(const float4*)(emb + (size_t)gv * D_ + ak4 * 4)
                            : make_float4(0.f, 0.f, 0.f, 0.f);
    }
#pragma unroll
    for (int r = 0; r < 4; r++) {
        int id = tid + 512 * r;
        int term = id >> 10;
        int e = id & 1023;
        int row = e >> 3, seg = e & 7;
        const char* src = (const char*)(term ? g_pnl2 : g_pnh2)
                        + (size_t)(tblk + row) * 1024 + seg * 16;
        uint32_t dst = sb + 32768 + term * 16384 + SW128((uint32_t)(row * 128 + seg * 16));
        CPASYNC16(dst, src);
    }
    CPCOMMIT();

    for (int c = 0; c < NCH; c++) {
        const int bb = c & 1;
        // ---- store A(c) from prefetch regs (convert to bf16 hi/lo) ----
#pragma unroll
        for (int l = 0; l < 4; l++) {
            float4 x = apre[l];
            int row = arow + 32 * l;
            uint32_t h01 = bf16x2_of(x.x, x.y), h23 = bf16x2_of(x.z, x.w);
            float l0 = x.x - __uint_as_float(h01 << 16);
            float l1 = x.y - __uint_as_float(h01 & 0xFFFF0000u);
            float l2 = x.z - __uint_as_float(h23 << 16);
            float l3 = x.w - __uint_as_float(h23 & 0xFFFF0000u);
            uint32_t l01 = bf16x2_of(l0, l1), l23 = bf16x2_of(l2, l3);
            uint32_t off = SW128((uint32_t)(row * 128 + ak4 * 8));
            asm volatile("st.shared.v2.b32 [%0], {%1,%2};" :: "r"(sb + AH + off), "r"(h01), "r"(h23));
            asm volatile("st.shared.v2.b32 [%0], {%1,%2};" :: "r"(sb + AL + off), "r"(l01), "r"(l23));
        }
        CPWAIT0();
        __syncthreads();
        // ---- issue next chunk's loads ----
        if (c < NCH - 1) {
            const int kb = (c + 1) * BKF;
#pragma unroll
            for (int r = 0; r < 4; r++) {
                int id = tid + 512 * r;
                int term = id >> 10;
                int e = id & 1023;
                int row = e >> 3, seg = e & 7;
                const char* src = (const char*)(term ? g_pnl2 : g_pnh2)
                                + (size_t)(tblk + row) * 1024 + (c + 1) * 128 + seg * 16;
                uint32_t dst = sb + 32768 + (bb ^ 1) * 32768 + term * 16384
                             + SW128((uint32_t)(row * 128 + seg * 16));
                CPASYNC16(dst, src);
            }
            CPCOMMIT();
#pragma unroll
            for (int l = 0; l < 4; l++) {
                int row = arow + 32 * l;
                int gv = vblk + row;
                apre[l] = (gv < V_) ? *(const float4*)(emb + (size_t)gv * D_ + kb + ak4 * 4)
                                    : make_float4(0.f, 0.f, 0.f, 0.f);
            }
        }
        // ---- compute chunk c ----
        const uint32_t BH = 32768 + bb * 32768, BL = BH + 16384;
#pragma unroll
        for (int s = 0; s < 4; s++) {
            const uint32_t akoff = (uint32_t)(s * 32 + a_kb);
            const uint32_t bkoff = (uint32_t)(s * 32 + b_kb);
            uint32_t ah[8], al8[8], bh[8], bl[8];
#pragma unroll
            for (int i = 0; i < 2; i++)
                ldsm4(&ah[i*4], sb + AH + SW128((uint32_t)((mw + i*16 + a_row) * 128) + akoff));
#pragma unroll
            for (int j2 = 0; j2 < 2; j2++)
                ldsm4(&bh[j2*4], sb + BH + SW128((uint32_t)((nw + j2*16 + b_row) * 128) + bkoff));
#pragma unroll
            for (int i = 0; i < 2; i++)
#pragma unroll
                for (int j = 0; j < 4; j++)
                    MMA16816(acc[i][j], &ah[i*4], bh[(j>>1)*4 + (j&1)*2], bh[(j>>1)*4 + (j&1)*2 + 1]);
#pragma unroll
            for (int j2 = 0; j2 < 2; j2++)
                ldsm4(&bl[j2*4], sb + BL + SW128((uint32_t)((nw + j2*16 + b_row) * 128) + bkoff));
#pragma unroll
            for (int i = 0; i < 2; i++)
#pragma unroll
                for (int j = 0; j < 4; j++)
                    MMA16816(acc[i][j], &ah[i*4], bl[(j>>1)*4 + (j&1)*2], bl[(j>>1)*4 + (j&1)*2 + 1]);
#pragma unroll
            for (int i = 0; i < 2; i++)
                ldsm4(&al8[i*4], sb + AL + SW128((uint32_t)((mw + i*16 + a_row) * 128) + akoff));
#pragma unroll
            for (int i = 0; i < 2; i++)
#pragma unroll
                for (int j = 0; j < 4; j++)
                    MMA16816(acc[i][j], &al8[i*4], bh[(j>>1)*4 + (j&1)*2], bh[(j>>1)*4 + (j&1)*2 + 1]);
        }
        __syncthreads();
    }

    // ---- epilogue: stage 64 tokens/phase, scale, store (scalar!), fused argmax ----
    float* cs = (float*)(smem + 32768);
    const int v4 = lane * 4;
    for (int p = 0; p < 2; p++) {
        __syncthreads();
        if ((nw & 64) == p * 64) {
#pragma unroll
            for (int i = 0; i < 2; i++)
#pragma unroll
                for (int j = 0; j < 4; j++) {
                    int v0 = mw + i * 16 + (lane >> 2);
                    int tl = (nw & 32) + j * 8 + (lane & 3) * 2;
                    cs[ tl      * 132 + v0    ] = acc[i][j][0];
                    cs[(tl + 1) * 132 + v0    ] = acc[i][j][1];
                    cs[ tl      * 132 + v0 + 8] = acc[i][j][2];
                    cs[(tl + 1) * 132 + v0 + 8] = acc[i][j][3];
                }
        }
        __syncthreads();
#pragma unroll
        for (int it = 0; it < 4; it++) {
            int tl = (tid >> 5) + it * 16;
            int gt = tblk + p * 64 + tl;
            float4 val = *(float4*)(cs + tl * 132 + v4);
            float4 e4  = *(const float4*)(g_inv_enorm + vblk + v4);
            val.x *= e4.x; val.y *= e4.y; val.z *= e4.z; val.w *= e4.w;
            int gv = vblk + v4;
            // scalar stores: sim row base gt*V_ is odd-aligned (V_ odd), float4 faults
            float* dst = simout + (size_t)gt * V_ + gv;
            if (gv     < V_) dst[0] = val.x;
            if (gv + 1 < V_) dst[1] = val.y;
            if (gv + 2 < V_) dst[2] = val.z;
            if (gv + 3 < V_) dst[3] = val.w;
            // fused partial argmax over this CTA's 128 v for token gt
            const float* nrow = noise + (size_t)gt * V_;
            float fs = -3e38f; int fv = 0;
            float e[4] = {val.x, val.y, val.z, val.w};
#pragma unroll
            for (int u = 0; u < 4; u++) {
                float sv = (gv + u < V_) ? e[u] : -3e38f;
                if (sv > fs) { fs = sv; fv = gv + u; }
                else if (sv == fs && sv > -3e38f) {
                    float n1 = nrow[fv], n2 = nrow[gv + u];
                    if (n2 > n1) fv = gv + u;
                }
            }
#pragma unroll
            for (int off = 16; off; off >>= 1) {
                float os = __shfl_xor_sync(0xffffffffu, fs, off);
                int   ov = __shfl_xor_sync(0xffffffffu, fv, off);
                bool take = os > fs;
                if (!take && os == fs && os > -3e38f) {
                    float n1 = nrow[fv], n2 = nrow[ov];
                    take = (n2 > n1) || (n2 == n1 && ov < fv);
                }
                if (take) { fs = os; fv = ov; }
            }
            if (lane == 0) {
                g_part_s[gt * NVB + blockIdx.y] = fs;
                g_part_i[gt * NVB + blockIdx.y] = fv;
            }
        }
    }
}

// ---------------- kernel 4: merge partials ----------------
__global__ void merge_kernel(const float* __restrict__ noise,
                             void* __restrict__ out, int write_float) {
    const int t = blockIdx.x, tid = threadIdx.x;   // 128 threads
    const float* ps = g_part_s + t * NVB;
    const int*   pi = g_part_i + t * NVB;

    float s = -3e38f;
    for (int j = tid; j < NVB; j += 128) s = fmaxf(s, ps[j]);
#pragma unroll
    for (int off = 16; off; off >>= 1) s = fmaxf(s, __shfl_xor_sync(0xffffffffu, s, off));
    __shared__ float sm[4];
    if ((tid & 31) == 0) sm[tid >> 5] = s;
    __syncthreads();
    float smax = fmaxf(fmaxf(sm[0], sm[1]), fmaxf(sm[2], sm[3]));

    const float* nrow = noise + (size_t)t * V_;
    float bn = -2.f; int bv = 0x7fffffff;
    for (int j = tid; j < NVB; j += 128) {
        if (ps[j] == smax) {
            int v = pi[j];
            float n = nrow[v];
            if (n > bn || (n == bn && v < bv)) { bn = n; bv = v; }
        }
    }
#pragma unroll
    for (int off = 16; off; off >>= 1) {
        float on = __shfl_xor_sync(0xffffffffu, bn, off);
        int   ov = __shfl_xor_sync(0xffffffffu, bv, off);
        if (on > bn || (on == bn && ov < bv)) { bn = on; bv = ov; }
    }
    __shared__ float nm[4]; __shared__ int vm[4];
    if ((tid & 31) == 0) { nm[tid >> 5] = bn; vm[tid >> 5] = bv; }
    __syncthreads();
    if (tid == 0) {
#pragma unroll
        for (int w = 1; w < 4; w++) {
            if (nm[w] > nm[0] || (nm[w] == nm[0] && vm[w] < vm[0])) { nm[0] = nm[w]; vm[0] = vm[w]; }
        }
        if (write_float) ((float*)out)[t] = (float)vm[0];
        else             ((int*)out)[t]   = vm[0];
    }
}

// ---------------- launcher ----------------
extern "C" void kernel_launch(void* const* d_in, const int* in_sizes, int n_in,
                              void* d_out, int out_size) {
    const int*   utt   = (const int*)d_in[0];
    const float* emb   = (const float*)d_in[1];
    const float* grad  = (const float*)d_in[2];
    const float* noise = (const float*)d_in[3];

    prep_kernel<<<BS_, 128>>>(utt, emb, grad);
    enorm_kernel<<<(V_ + 7) / 8, 256>>>(emb);

    const long long SIMN = (long long)BS_ * V_;
    float* simptr;
    float* simscr;
    cudaGetSymbolAddress((void**)&simscr, g_sim_scratch);
    if ((long long)out_size == SIMN + BS_)      simptr = (float*)d_out + BS_;
    else if ((long long)out_size == SIMN)       simptr = (float*)d_out;
    else                                        simptr = simscr;

    cudaFuncSetAttribute(gemm_kernel, cudaFuncAttributeMaxDynamicSharedMemorySize, 98304);
    dim3 grid(BS_ / BN, NVB);
    gemm_kernel<<<grid, 512, 98304>>>(emb, simptr, noise);

    if ((long long)out_size == SIMN + BS_)
        merge_kernel<<<BS_, 128>>>(noise, d_out, 1);
    else if (out_size == BS_)
        merge_kernel<<<BS_, 128>>>(noise, d_out, 0);
}

// round 9
// speedup vs baseline: 2.9690x; 1.2246x over previous
#include <cuda_runtime.h>
#include <cuda_fp16.h>
#include <cstdint>

#define V_    50257
#define VPAD  50304
#define NVB   393          // vocab blocks
#define BS_   512
#define D_    512
#define BM    128
#define BN    128
#define BKF   64
#define NCH   (D_/BKF)

__device__ __align__(16) uint2 g_pnh2[BS_*D_/4];   // pn hi fp16 pairs [t][k/4]
__device__ __align__(16) uint2 g_pnl2[BS_*D_/4];   // pn lo fp16 pairs
__device__ float g_sim_scratch[(size_t)BS_*V_];
__device__ float g_part_s[BS_*NVB];
__device__ int   g_part_i[BS_*NVB];

#define SW128(x) ((x) ^ (((x) >> 3) & 0x70))

__device__ __forceinline__ uint32_t smem_u32(const void* p){
    uint32_t a;
    asm("{ .reg .u64 t; cvta.to.shared.u64 t, %1; cvt.u32.u64 %0, t; }" : "=r"(a) : "l"(p));
    return a;
}
__device__ __forceinline__ uint32_t f16x2_of(float lo, float hi){
    __half2 h = __floats2half2_rn(lo, hi);
    return *(uint32_t*)&h;
}
__device__ __forceinline__ void ldsm4(uint32_t* r, uint32_t addr){
    asm volatile("ldmatrix.sync.aligned.m8n8.x4.shared.b16 {%0,%1,%2,%3}, [%4];"
        : "=r"(r[0]), "=r"(r[1]), "=r"(r[2]), "=r"(r[3]) : "r"(addr));
}
#define MMA16816(c, a, b0v, b1v) \
    asm volatile("mma.sync.aligned.m16n8k16.row.col.f32.f16.f16.f32 " \
        "{%0,%1,%2,%3}, {%4,%5,%6,%7}, {%8,%9}, {%0,%1,%2,%3};" \
        : "+f"((c)[0]), "+f"((c)[1]), "+f"((c)[2]), "+f"((c)[3]) \
        : "r"((a)[0]), "r"((a)[1]), "r"((a)[2]), "r"((a)[3]), "r"(b0v), "r"(b1v))
#define CPASYNC16(dst, src) \
    asm volatile("cp.async.cg.shared.global [%0], [%1], 16;" :: "r"(dst), "l"(src))
#define CPCOMMIT() asm volatile("cp.async.commit_group;" ::: "memory")
#define CPWAIT0()  asm volatile("cp.async.wait_group 0;" ::: "memory")

// ---------------- kernel 1: perturb + normalize + fp16 hi/lo split ----------------
__global__ void prep_kernel(const int* __restrict__ utt, const float* __restrict__ emb,
                            const float* __restrict__ grad) {
    const int t = blockIdx.x, tid = threadIdx.x;  // 128 threads
    const int token = utt[t];
    float4 e = *(const float4*)(emb + (size_t)token * D_ + tid * 4);
    float4 g = *(const float4*)(grad + (size_t)t * D_ + tid * 4);
    float p0 = e.x + 0.4f * ((g.x > 0.f) ? 1.f : ((g.x < 0.f) ? -1.f : 0.f));
    float p1 = e.y + 0.4f * ((g.y > 0.f) ? 1.f : ((g.y < 0.f) ? -1.f : 0.f));
    float p2 = e.z + 0.4f * ((g.z > 0.f) ? 1.f : ((g.z < 0.f) ? -1.f : 0.f));
    float p3 = e.w + 0.4f * ((g.w > 0.f) ? 1.f : ((g.w < 0.f) ? -1.f : 0.f));
    float ss = p0*p0 + p1*p1 + p2*p2 + p3*p3;
#pragma unroll
    for (int off = 16; off; off >>= 1) ss += __shfl_xor_sync(0xffffffffu, ss, off);
    __shared__ float wsum[4];
    if ((tid & 31) == 0) wsum[tid >> 5] = ss;
    __syncthreads();
    float inv = 1.f / fmaxf(sqrtf(wsum[0] + wsum[1] + wsum[2] + wsum[3]), 1e-8f);
    p0 *= inv; p1 *= inv; p2 *= inv; p3 *= inv;

    __half h0 = __float2half_rn(p0), h1 = __float2half_rn(p1);
    __half h2 = __float2half_rn(p2), h3 = __float2half_rn(p3);
    float l0 = p0 - __half2float(h0);
    float l1 = p1 - __half2float(h1);
    float l2 = p2 - __half2float(h2);
    float l3 = p3 - __half2float(h3);
    __half2 hh01 = __halves2half2(h0, h1), hh23 = __halves2half2(h2, h3);
    g_pnh2[t * 128 + tid] = make_uint2(*(uint32_t*)&hh01, *(uint32_t*)&hh23);
    g_pnl2[t * 128 + tid] = make_uint2(f16x2_of(l0, l1), f16x2_of(l2, l3));
}

// ---------------- kernel 2: pipelined fp16 2-term GEMM + fused norms + argmax ----
// C[v][t] = emb_h[v] . (pn_h[t] + pn_l[t]);  scaled by 1/||emb_v|| computed in-kernel
__global__ void __launch_bounds__(512) gemm_kernel(const float* __restrict__ emb,
                                                   float* __restrict__ simout,
                                                   const float* __restrict__ noise) {
    extern __shared__ char smem[];
    const uint32_t sb = smem_u32(smem);
    const int tid = threadIdx.x;
    const int wid = tid >> 5, lane = tid & 31;
    const int tblk = blockIdx.x * BN;
    const int vblk = blockIdx.y * BM;

    const uint32_t AH = 0;                 // A fp16 tile: 128 x 64 x 2B = 16 KB
    // B buffers at 16384 + buf*32768 + term*16384  (total 64 KB)
    const uint32_t SINV = 81920;           // float[128] inv norms

    float acc[2][4][4];
#pragma unroll
    for (int i = 0; i < 2; i++)
#pragma unroll
        for (int j = 0; j < 4; j++)
#pragma unroll
            for (int q = 0; q < 4; q++) acc[i][j][q] = 0.f;

    const int mw = (wid >> 2) * 32;
    const int nw = (wid & 3) * 32;
    const int a_row = (lane & 7) + ((lane >> 3) & 1) * 8;
    const int a_kb  = ((lane >> 4) & 1) * 16;
    const int b_row = (lane & 7) + ((lane >> 4) & 1) * 8;
    const int b_kb  = ((lane >> 3) & 1) * 16;

    const int arow = tid >> 4;
    const int ak4  = tid & 15;

    float ssq[4] = {0.f, 0.f, 0.f, 0.f};   // per-thread partial sumsq of emb rows

    // ---- preamble: issue B(0), prefetch A(0) ----
    float4 apre[4];
#pragma unroll
    for (int l = 0; l < 4; l++) {
        int row = arow + 32 * l;
        int gv = vblk + row;
        apre[l] = (gv < V_) ? *(const float4*)(emb + (size_t)gv * D_ + ak4 * 4)
                            : make_float4(0.f, 0.f, 0.f, 0.f);
    }
#pragma unroll
    for (int r = 0; r < 4; r++) {
        int id = tid + 512 * r;
        int term = id >> 10;
        int e = id & 1023;
        int row = e >> 3, seg = e & 7;
        const char* src = (const char*)(term ? g_pnl2 : g_pnh2)
                        + (size_t)(tblk + row) * 1024 + seg * 16;
        uint32_t dst = sb + 16384 + term * 16384 + SW128((uint32_t)(row * 128 + seg * 16));
        CPASYNC16(dst, src);
    }
    CPCOMMIT();

    for (int c = 0; c < NCH; c++) {
        const int bb = c & 1;
        // ---- store A(c): fp32 -> single fp16, accumulate sumsq ----
#pragma unroll
        for (int l = 0; l < 4; l++) {
            float4 x = apre[l];
            ssq[l] += x.x*x.x + x.y*x.y + x.z*x.z + x.w*x.w;
            int row = arow + 32 * l;
            uint32_t h01 = f16x2_of(x.x, x.y), h23 = f16x2_of(x.z, x.w);
            uint32_t off = SW128((uint32_t)(row * 128 + ak4 * 8));
            asm volatile("st.shared.v2.b32 [%0], {%1,%2};" :: "r"(sb + AH + off), "r"(h01), "r"(h23));
        }
        CPWAIT0();
        __syncthreads();
        // ---- issue next chunk's loads ----
        if (c < NCH - 1) {
            const int kb = (c + 1) * BKF;
#pragma unroll
            for (int r = 0; r < 4; r++) {
                int id = tid + 512 * r;
                int term = id >> 10;
                int e = id & 1023;
                int row = e >> 3, seg = e & 7;
                const char* src = (const char*)(term ? g_pnl2 : g_pnh2)
                                + (size_t)(tblk + row) * 1024 + (c + 1) * 128 + seg * 16;
                uint32_t dst = sb + 16384 + (bb ^ 1) * 32768 + term * 16384
                             + SW128((uint32_t)(row * 128 + seg * 16));
                CPASYNC16(dst, src);
            }
            CPCOMMIT();
#pragma unroll
            for (int l = 0; l < 4; l++) {
                int row = arow + 32 * l;
                int gv = vblk + row;
                apre[l] = (gv < V_) ? *(const float4*)(emb + (size_t)gv * D_ + kb + ak4 * 4)
                                    : make_float4(0.f, 0.f, 0.f, 0.f);
            }
        }
        // ---- compute chunk c: 4 k16-steps x 2 terms ----
        const uint32_t BH = 16384 + bb * 32768, BL = BH + 16384;
#pragma unroll
        for (int s = 0; s < 4; s++) {
            const uint32_t akoff = (uint32_t)(s * 32 + a_kb);
            const uint32_t bkoff = (uint32_t)(s * 32 + b_kb);
            uint32_t ah[8], bh[8], bl[8];
#pragma unroll
            for (int i = 0; i < 2; i++)
                ldsm4(&ah[i*4], sb + AH + SW128((uint32_t)((mw + i*16 + a_row) * 128) + akoff));
#pragma unroll
            for (int j2 = 0; j2 < 2; j2++)
                ldsm4(&bh[j2*4], sb + BH + SW128((uint32_t)((nw + j2*16 + b_row) * 128) + bkoff));
#pragma unroll
            for (int i = 0; i < 2; i++)
#pragma unroll
                for (int j = 0; j < 4; j++)
                    MMA16816(acc[i][j], &ah[i*4], bh[(j>>1)*4 + (j&1)*2], bh[(j>>1)*4 + (j&1)*2 + 1]);
#pragma unroll
            for (int j2 = 0; j2 < 2; j2++)
                ldsm4(&bl[j2*4], sb + BL + SW128((uint32_t)((nw + j2*16 + b_row) * 128) + bkoff));
#pragma unroll
            for (int i = 0; i < 2; i++)
#pragma unroll
                for (int j = 0; j < 4; j++)
                    MMA16816(acc[i][j], &ah[i*4], bl[(j>>1)*4 + (j&1)*2], bl[(j>>1)*4 + (j&1)*2 + 1]);
        }
        __syncthreads();
    }

    // ---- finish row norms: reduce ssq over the 16 ak4 lanes, write to smem ----
    float* sInv = (float*)(smem + SINV);
#pragma unroll
    for (int l = 0; l < 4; l++) {
        float s = ssq[l];
#pragma unroll
        for (int off = 1; off < 16; off <<= 1)
            s += __shfl_xor_sync(0xffffffffu, s, off);
        if (ak4 == 0) sInv[arow + 32 * l] = 1.f / fmaxf(sqrtf(s), 1e-8f);
    }
    __syncthreads();

    // ---- epilogue: stage 64 tokens/phase, scale, store (scalar), fused argmax ----
    float* cs = (float*)(smem + 16384);
    const int v4 = lane * 4;
    for (int p = 0; p < 2; p++) {
        __syncthreads();
        if ((nw & 64) == p * 64) {
#pragma unroll
            for (int i = 0; i < 2; i++)
#pragma unroll
                for (int j = 0; j < 4; j++) {
                    int v0 = mw + i * 16 + (lane >> 2);
                    int tl = (nw & 32) + j * 8 + (lane & 3) * 2;
                    cs[ tl      * 132 + v0    ] = acc[i][j][0];
                    cs[(tl + 1) * 132 + v0    ] = acc[i][j][1];
                    cs[ tl      * 132 + v0 + 8] = acc[i][j][2];
                    cs[(tl + 1) * 132 + v0 + 8] = acc[i][j][3];
                }
        }
        __syncthreads();
#pragma unroll
        for (int it = 0; it < 4; it++) {
            int tl = (tid >> 5) + it * 16;
            int gt = tblk + p * 64 + tl;
            float4 val = *(float4*)(cs + tl * 132 + v4);
            val.x *= sInv[v4];
            val.y *= sInv[v4 + 1];
            val.z *= sInv[v4 + 2];
            val.w *= sInv[v4 + 3];
            int gv = vblk + v4;
            // scalar stores: sim row base gt*V_ only 4B aligned (V_ odd)
            float* dst = simout + (size_t)gt * V_ + gv;
            if (gv     < V_) dst[0] = val.x;
            if (gv + 1 < V_) dst[1] = val.y;
            if (gv + 2 < V_) dst[2] = val.z;
            if (gv + 3 < V_) dst[3] = val.w;
            // fused partial argmax over this CTA's 128 v for token gt
            const float* nrow = noise + (size_t)gt * V_;
            float fs = -3e38f; int fv = 0;
            float e[4] = {val.x, val.y, val.z, val.w};
#pragma unroll
            for (int u = 0; u < 4; u++) {
                float sv = (gv + u < V_) ? e[u] : -3e38f;
                if (sv > fs) { fs = sv; fv = gv + u; }
                else if (sv == fs && sv > -3e38f) {
                    float n1 = nrow[fv], n2 = nrow[gv + u];
                    if (n2 > n1) fv = gv + u;
                }
            }
#pragma unroll
            for (int off = 16; off; off >>= 1) {
                float os = __shfl_xor_sync(0xffffffffu, fs, off);
                int   ov = __shfl_xor_sync(0xffffffffu, fv, off);
                bool take = os > fs;
                if (!take && os == fs && os > -3e38f) {
                    float n1 = nrow[fv], n2 = nrow[ov];
                    take = (n2 > n1) || (n2 == n1 && ov < fv);
                }
                if (take) { fs = os; fv = ov; }
            }
            if (lane == 0) {
                g_part_s[gt * NVB + blockIdx.y] = fs;
                g_part_i[gt * NVB + blockIdx.y] = fv;
            }
        }
    }
}

// ---------------- kernel 3: merge partials ----------------
__global__ void merge_kernel(const float* __restrict__ noise,
                             void* __restrict__ out, int write_float) {
    const int t = blockIdx.x, tid = threadIdx.x;   // 128 threads
    const float* ps = g_part_s + t * NVB;
    const int*   pi = g_part_i + t * NVB;

    float s = -3e38f;
    for (int j = tid; j < NVB; j += 128) s = fmaxf(s, ps[j]);
#pragma unroll
    for (int off = 16; off; off >>= 1) s = fmaxf(s, __shfl_xor_sync(0xffffffffu, s, off));
    __shared__ float sm[4];
    if ((tid & 31) == 0) sm[tid >> 5] = s;
    __syncthreads();
    float smax = fmaxf(fmaxf(sm[0], sm[1]), fmaxf(sm[2], sm[3]));

    const float* nrow = noise + (size_t)t * V_;
    float bn = -2.f; int bv = 0x7fffffff;
    for (int j = tid; j < NVB; j += 128) {
        if (ps[j] == smax) {
            int v = pi[j];
            float n = nrow[v];
            if (n > bn || (n == bn && v < bv)) { bn = n; bv = v; }
        }
    }
#pragma unroll
    for (int off = 16; off; off >>= 1) {
        float on = __shfl_xor_sync(0xffffffffu, bn, off);
        int   ov = __shfl_xor_sync(0xffffffffu, bv, off);
        if (on > bn || (on == bn && ov < bv)) { bn = on; bv = ov; }
    }
    __shared__ float nm[4]; __shared__ int vm[4];
    if ((tid & 31) == 0) { nm[tid >> 5] = bn; vm[tid >> 5] = bv; }
    __syncthreads();
    if (tid == 0) {
#pragma unroll
        for (int w = 1; w < 4; w++) {
            if (nm[w] > nm[0] || (nm[w] == nm[0] && vm[w] < vm[0])) { nm[0] = nm[w]; vm[0] = vm[w]; }
        }
        if (write_float) ((float*)out)[t] = (float)vm[0];
        else             ((int*)out)[t]   = vm[0];
    }
}

// ---------------- launcher ----------------
extern "C" void kernel_launch(void* const* d_in, const int* in_sizes, int n_in,
                              void* d_out, int out_size) {
    const int*   utt   = (const int*)d_in[0];
    const float* emb   = (const float*)d_in[1];
    const float* grad  = (const float*)d_in[2];
    const float* noise = (const float*)d_in[3];

    prep_kernel<<<BS_, 128>>>(utt, emb, grad);

    const long long SIMN = (long long)BS_ * V_;
    float* simptr;
    float* simscr;
    cudaGetSymbolAddress((void**)&simscr, g_sim_scratch);
    if ((long long)out_size == SIMN + BS_)      simptr = (float*)d_out + BS_;
    else if ((long long)out_size == SIMN)       simptr = (float*)d_out;
    else                                        simptr = simscr;

    cudaFuncSetAttribute(gemm_kernel, cudaFuncAttributeMaxDynamicSharedMemorySize, 82432);
    dim3 grid(BS_ / BN, NVB);
    gemm_kernel<<<grid, 512, 82432>>>(emb, simptr, noise);

    if ((long long)out_size == SIMN + BS_)
        merge_kernel<<<BS_, 128>>>(noise, d_out, 1);
    else if (out_size == BS_)
        merge_kernel<<<BS_, 128>>>(noise, d_out, 0);
}

// round 11
// speedup vs baseline: 3.6600x; 1.2328x over previous
#include <cuda_runtime.h>
#include <cuda_fp16.h>
#include <cstdint>

#define V_    50257
#define VPAD  50304
#define NVB   393          // vocab blocks
#define BS_   512
#define D_    512
#define BM    128
#define BN    128
#define BKF   64
#define NCH   (D_/BKF)

__device__ __align__(16) uint2 g_pnh2[BS_*D_/4];   // pn fp16 pairs [t][k/4]
__device__ float g_sim_scratch[(size_t)BS_*V_];
__device__ float g_part_s[BS_*NVB];
__device__ int   g_part_i[BS_*NVB];

#define SW128(x) ((x) ^ (((x) >> 3) & 0x70))

__device__ __forceinline__ uint32_t smem_u32(const void* p){
    uint32_t a;
    asm("{ .reg .u64 t; cvta.to.shared.u64 t, %1; cvt.u32.u64 %0, t; }" : "=r"(a) : "l"(p));
    return a;
}
__device__ __forceinline__ uint32_t f16x2_of(float lo, float hi){
    __half2 h = __floats2half2_rn(lo, hi);
    return *(uint32_t*)&h;
}
__device__ __forceinline__ void ldsm4(uint32_t* r, uint32_t addr){
    asm volatile("ldmatrix.sync.aligned.m8n8.x4.shared.b16 {%0,%1,%2,%3}, [%4];"
        : "=r"(r[0]), "=r"(r[1]), "=r"(r[2]), "=r"(r[3]) : "r"(addr));
}
#define MMA16816(c, a, b0v, b1v) \
    asm volatile("mma.sync.aligned.m16n8k16.row.col.f32.f16.f16.f32 " \
        "{%0,%1,%2,%3}, {%4,%5,%6,%7}, {%8,%9}, {%0,%1,%2,%3};" \
        : "+f"((c)[0]), "+f"((c)[1]), "+f"((c)[2]), "+f"((c)[3]) \
        : "r"((a)[0]), "r"((a)[1]), "r"((a)[2]), "r"((a)[3]), "r"(b0v), "r"(b1v))
#define CPASYNC16(dst, src) \
    asm volatile("cp.async.cg.shared.global [%0], [%1], 16;" :: "r"(dst), "l"(src))
#define CPCOMMIT() asm volatile("cp.async.commit_group;" ::: "memory")
#define CPWAIT0()  asm volatile("cp.async.wait_group 0;" ::: "memory")

// ---------------- kernel 1: perturb + normalize + fp16 ----------------
__global__ void prep_kernel(const int* __restrict__ utt, const float* __restrict__ emb,
                            const float* __restrict__ grad) {
    const int t = blockIdx.x, tid = threadIdx.x;  // 128 threads
    const int token = utt[t];
    float4 e = *(const float4*)(emb + (size_t)token * D_ + tid * 4);
    float4 g = *(const float4*)(grad + (size_t)t * D_ + tid * 4);
    float p0 = e.x + 0.4f * ((g.x > 0.f) ? 1.f : ((g.x < 0.f) ? -1.f : 0.f));
    float p1 = e.y + 0.4f * ((g.y > 0.f) ? 1.f : ((g.y < 0.f) ? -1.f : 0.f));
    float p2 = e.z + 0.4f * ((g.z > 0.f) ? 1.f : ((g.z < 0.f) ? -1.f : 0.f));
    float p3 = e.w + 0.4f * ((g.w > 0.f) ? 1.f : ((g.w < 0.f) ? -1.f : 0.f));
    float ss = p0*p0 + p1*p1 + p2*p2 + p3*p3;
#pragma unroll
    for (int off = 16; off; off >>= 1) ss += __shfl_xor_sync(0xffffffffu, ss, off);
    __shared__ float wsum[4];
    if ((tid & 31) == 0) wsum[tid >> 5] = ss;
    __syncthreads();
    float inv = 1.f / fmaxf(sqrtf(wsum[0] + wsum[1] + wsum[2] + wsum[3]), 1e-8f);
    p0 *= inv; p1 *= inv; p2 *= inv; p3 *= inv;
    g_pnh2[t * 128 + tid] = make_uint2(f16x2_of(p0, p1), f16x2_of(p2, p3));
}

// ---------------- kernel 2: pipelined fp16 GEMM + fused norms + argmax ----
// C[v][t] = fp16(emb[v]) . fp16(pn[t]);  scaled by 1/||emb_v|| computed in-kernel
__global__ void __launch_bounds__(512) gemm_kernel(const float* __restrict__ emb,
                                                   float* __restrict__ simout,
                                                   const float* __restrict__ noise) {
    extern __shared__ char smem[];
    const uint32_t sb = smem_u32(smem);
    const int tid = threadIdx.x;
    const int wid = tid >> 5, lane = tid & 31;
    const int tblk = blockIdx.x * BN;
    const int vblk = blockIdx.y * BM;

    const uint32_t AH = 0;                 // A fp16 tile: 128 x 64 x 2B = 16 KB
    // B buffers: 16384 + buf*16384 (two 16 KB buffers)
    const uint32_t SINV = 49152;           // float[128] inv norms

    float acc[2][4][4];
#pragma unroll
    for (int i = 0; i < 2; i++)
#pragma unroll
        for (int j = 0; j < 4; j++)
#pragma unroll
            for (int q = 0; q < 4; q++) acc[i][j][q] = 0.f;

    const int mw = (wid >> 2) * 32;
    const int nw = (wid & 3) * 32;
    const int a_row = (lane & 7) + ((lane >> 3) & 1) * 8;
    const int a_kb  = ((lane >> 4) & 1) * 16;
    const int b_row = (lane & 7) + ((lane >> 4) & 1) * 8;
    const int b_kb  = ((lane >> 3) & 1) * 16;

    const int arow = tid >> 4;
    const int ak4  = tid & 15;

    float ssq[4] = {0.f, 0.f, 0.f, 0.f};

    // ---- preamble: issue B(0), prefetch A(0) ----
    float4 apre[4];
#pragma unroll
    for (int l = 0; l < 4; l++) {
        int row = arow + 32 * l;
        int gv = vblk + row;
        apre[l] = (gv < V_) ? *(const float4*)(emb + (size_t)gv * D_ + ak4 * 4)
                            : make_float4(0.f, 0.f, 0.f, 0.f);
    }
#pragma unroll
    for (int r = 0; r < 2; r++) {
        int id = tid + 512 * r;
        int row = id >> 3, seg = id & 7;
        const char* src = (const char*)g_pnh2 + (size_t)(tblk + row) * 1024 + seg * 16;
        uint32_t dst = sb + 16384 + SW128((uint32_t)(row * 128 + seg * 16));
        CPASYNC16(dst, src);
    }
    CPCOMMIT();

    for (int c = 0; c < NCH; c++) {
        const int bb = c & 1;
        // ---- store A(c): fp32 -> fp16, accumulate sumsq ----
#pragma unroll
        for (int l = 0; l < 4; l++) {
            float4 x = apre[l];
            ssq[l] += x.x*x.x + x.y*x.y + x.z*x.z + x.w*x.w;
            int row = arow + 32 * l;
            uint32_t h01 = f16x2_of(x.x, x.y), h23 = f16x2_of(x.z, x.w);
            uint32_t off = SW128((uint32_t)(row * 128 + ak4 * 8));
            asm volatile("st.shared.v2.b32 [%0], {%1,%2};" :: "r"(sb + AH + off), "r"(h01), "r"(h23));
        }
        CPWAIT0();
        __syncthreads();
        // ---- issue next chunk's B loads, prefetch next A ----
        if (c < NCH - 1) {
            const int kb = (c + 1) * BKF;
#pragma unroll
            for (int r = 0; r < 2; r++) {
                int id = tid + 512 * r;
                int row = id >> 3, seg = id & 7;
                const char* src = (const char*)g_pnh2 + (size_t)(tblk + row) * 1024
                                + (c + 1) * 128 + seg * 16;
                uint32_t dst = sb + 16384 + (bb ^ 1) * 16384
                             + SW128((uint32_t)(row * 128 + seg * 16));
                CPASYNC16(dst, src);
            }
            CPCOMMIT();
#pragma unroll
            for (int l = 0; l < 4; l++) {
                int row = arow + 32 * l;
                int gv = vblk + row;
                apre[l] = (gv < V_) ? *(const float4*)(emb + (size_t)gv * D_ + kb + ak4 * 4)
                                    : make_float4(0.f, 0.f, 0.f, 0.f);
            }
        }
        // ---- compute chunk c: 4 k16-steps, single term ----
        const uint32_t BH = 16384 + bb * 16384;
#pragma unroll
        for (int s = 0; s < 4; s++) {
            const uint32_t akoff = (uint32_t)(s * 32 + a_kb);
            const uint32_t bkoff = (uint32_t)(s * 32 + b_kb);
            uint32_t ah[8], bh[8];
#pragma unroll
            for (int i = 0; i < 2; i++)
                ldsm4(&ah[i*4], sb + AH + SW128((uint32_t)((mw + i*16 + a_row) * 128) + akoff));
#pragma unroll
            for (int j2 = 0; j2 < 2; j2++)
                ldsm4(&bh[j2*4], sb + BH + SW128((uint32_t)((nw + j2*16 + b_row) * 128) + bkoff));
#pragma unroll
            for (int i = 0; i < 2; i++)
#pragma unroll
                for (int j = 0; j < 4; j++)
                    MMA16816(acc[i][j], &ah[i*4], bh[(j>>1)*4 + (j&1)*2], bh[(j>>1)*4 + (j&1)*2 + 1]);
        }
        __syncthreads();
    }

    // ---- finish row norms ----
    float* sInv = (float*)(smem + SINV);
#pragma unroll
    for (int l = 0; l < 4; l++) {
        float s = ssq[l];
#pragma unroll
        for (int off = 1; off < 16; off <<= 1)
            s += __shfl_xor_sync(0xffffffffu, s, off);
        if (ak4 == 0) sInv[arow + 32 * l] = 1.f / fmaxf(sqrtf(s), 1e-8f);
    }
    __syncthreads();

    // ---- epilogue: stage 64 tokens/phase (cs overlaps A+B, now dead), fused argmax --
    float* cs = (float*)smem;              // [64][132] floats = 33792 B
    const int v4 = lane * 4;
    for (int p = 0; p < 2; p++) {
        __syncthreads();
        if ((nw & 64) == p * 64) {
#pragma unroll
            for (int i = 0; i < 2; i++)
#pragma unroll
                for (int j = 0; j < 4; j++) {
                    int v0 = mw + i * 16 + (lane >> 2);
                    int tl = (nw & 32) + j * 8 + (lane & 3) * 2;
                    cs[ tl      * 132 + v0    ] = acc[i][j][0];
                    cs[(tl + 1) * 132 + v0    ] = acc[i][j][1];
                    cs[ tl      * 132 + v0 + 8] = acc[i][j][2];
                    cs[(tl + 1) * 132 + v0 + 8] = acc[i][j][3];
                }
        }
        __syncthreads();
#pragma unroll
        for (int it = 0; it < 4; it++) {
            int tl = (tid >> 5) + it * 16;
            int gt = tblk + p * 64 + tl;
            float4 val = *(float4*)(cs + tl * 132 + v4);
            val.x *= sInv[v4];
            val.y *= sInv[v4 + 1];
            val.z *= sInv[v4 + 2];
            val.w *= sInv[v4 + 3];
            int gv = vblk + v4;
            // scalar stores: sim row base gt*V_ only 4B aligned (V_ odd)
            float* dst = simout + (size_t)gt * V_ + gv;
            if (gv     < V_) dst[0] = val.x;
            if (gv + 1 < V_) dst[1] = val.y;
            if (gv + 2 < V_) dst[2] = val.z;
            if (gv + 3 < V_) dst[3] = val.w;
            // fused partial argmax over this CTA's 128 v for token gt
            const float* nrow = noise + (size_t)gt * V_;
            float fs = -3e38f; int fv = 0;
            float e[4] = {val.x, val.y, val.z, val.w};
#pragma unroll
            for (int u = 0; u < 4; u++) {
                float sv = (gv + u < V_) ? e[u] : -3e38f;
                if (sv > fs) { fs = sv; fv = gv + u; }
                else if (sv == fs && sv > -3e38f) {
                    float n1 = nrow[fv], n2 = nrow[gv + u];
                    if (n2 > n1) fv = gv + u;
                }
            }
#pragma unroll
            for (int off = 16; off; off >>= 1) {
                float os = __shfl_xor_sync(0xffffffffu, fs, off);
                int   ov = __shfl_xor_sync(0xffffffffu, fv, off);
                bool take = os > fs;
                if (!take && os == fs && os > -3e38f) {
                    float n1 = nrow[fv], n2 = nrow[ov];
                    take = (n2 > n1) || (n2 == n1 && ov < fv);
                }
                if (take) { fs = os; fv = ov; }
            }
            if (lane == 0) {
                g_part_s[gt * NVB + blockIdx.y] = fs;
                g_part_i[gt * NVB + blockIdx.y] = fv;
            }
        }
    }
}

// ---------------- kernel 3: merge partials ----------------
__global__ void merge_kernel(const float* __restrict__ noise,
                             void* __restrict__ out, int write_float) {
    const int t = blockIdx.x, tid = threadIdx.x;   // 128 threads
    const float* ps = g_part_s + t * NVB;
    const int*   pi = g_part_i + t * NVB;

    float s = -3e38f;
    for (int j = tid; j < NVB; j += 128) s = fmaxf(s, ps[j]);
#pragma unroll
    for (int off = 16; off; off >>= 1) s = fmaxf(s, __shfl_xor_sync(0xffffffffu, s, off));
    __shared__ float sm[4];
    if ((tid & 31) == 0) sm[tid >> 5] = s;
    __syncthreads();
    float smax = fmaxf(fmaxf(sm[0], sm[1]), fmaxf(sm[2], sm[3]));

    const float* nrow = noise + (size_t)t * V_;
    float bn = -2.f; int bv = 0x7fffffff;
    for (int j = tid; j < NVB; j += 128) {
        if (ps[j] == smax) {
            int v = pi[j];
            float n = nrow[v];
            if (n > bn || (n == bn && v < bv)) { bn = n; bv = v; }
        }
    }
#pragma unroll
    for (int off = 16; off; off >>= 1) {
        float on = __shfl_xor_sync(0xffffffffu, bn, off);
        int   ov = __shfl_xor_sync(0xffffffffu, bv, off);
        if (on > bn || (on == bn && ov < bv)) { bn = on; bv = ov; }
    }
    __shared__ float nm[4]; __shared__ int vm[4];
    if ((tid & 31) == 0) { nm[tid >> 5] = bn; vm[tid >> 5] = bv; }
    __syncthreads();
    if (tid == 0) {
#pragma unroll
        for (int w = 1; w < 4; w++) {
            if (nm[w] > nm[0] || (nm[w] == nm[0] && vm[w] < vm[0])) { nm[0] = nm[w]; vm[0] = vm[w]; }
        }
        if (write_float) ((float*)out)[t] = (float)vm[0];
        else             ((int*)out)[t]   = vm[0];
    }
}

// ---------------- launcher ----------------
extern "C" void kernel_launch(void* const* d_in, const int* in_sizes, int n_in,
                              void* d_out, int out_size) {
    const int*   utt   = (const int*)d_in[0];
    const float* emb   = (const float*)d_in[1];
    const float* grad  = (const float*)d_in[2];
    const float* noise = (const float*)d_in[3];

    prep_kernel<<<BS_, 128>>>(utt, emb, grad);

    const long long SIMN = (long long)BS_ * V_;
    float* simptr;
    float* simscr;
    cudaGetSymbolAddress((void**)&simscr, g_sim_scratch);
    if ((long long)out_size == SIMN + BS_)      simptr = (float*)d_out + BS_;
    else if ((long long)out_size == SIMN)       simptr = (float*)d_out;
    else                                        simptr = simscr;

    cudaFuncSetAttribute(gemm_kernel, cudaFuncAttributeMaxDynamicSharedMemorySize, 49664);
    dim3 grid(BS_ / BN, NVB);
    gemm_kernel<<<grid, 512, 49664>>>(emb, simptr, noise);

    if ((long long)out_size == SIMN + BS_)
        merge_kernel<<<BS_, 128>>>(noise, d_out, 1);
    else if (out_size == BS_)
        merge_kernel<<<BS_, 128>>>(noise, d_out, 0);
}

// round 13
// speedup vs baseline: 4.2719x; 1.1672x over previous
#include <cuda_runtime.h>
#include <cuda_fp16.h>
#include <cstdint>

#define V_    50257
#define VPAD  50304
#define NVB   393          // vocab blocks
#define BS_   512
#define D_    512
#define BM    128
#define BN    128
#define BKF   64
#define NCH   (D_/BKF)

__device__ __align__(16) uint2 g_pnh2[BS_*D_/4];       // pn fp16 pairs [t][k/4]
__device__ __align__(16) __half g_embh[(size_t)VPAD*D_]; // emb fp16 (rows >= V_ stay 0)
__device__ float g_inv_enorm[VPAD];
__device__ float g_sim_scratch[(size_t)BS_*V_];
__device__ float g_part_s[BS_*NVB];
__device__ int   g_part_i[BS_*NVB];

#define SW128(x) ((x) ^ (((x) >> 3) & 0x70))

__device__ __forceinline__ uint32_t smem_u32(const void* p){
    uint32_t a;
    asm("{ .reg .u64 t; cvta.to.shared.u64 t, %1; cvt.u32.u64 %0, t; }" : "=r"(a) : "l"(p));
    return a;
}
__device__ __forceinline__ uint32_t f16x2_of(float lo, float hi){
    __half2 h = __floats2half2_rn(lo, hi);
    return *(uint32_t*)&h;
}
__device__ __forceinline__ void ldsm4(uint32_t* r, uint32_t addr){
    asm volatile("ldmatrix.sync.aligned.m8n8.x4.shared.b16 {%0,%1,%2,%3}, [%4];"
        : "=r"(r[0]), "=r"(r[1]), "=r"(r[2]), "=r"(r[3]) : "r"(addr));
}
#define MMA16816(c, a, b0v, b1v) \
    asm volatile("mma.sync.aligned.m16n8k16.row.col.f32.f16.f16.f32 " \
        "{%0,%1,%2,%3}, {%4,%5,%6,%7}, {%8,%9}, {%0,%1,%2,%3};" \
        : "+f"((c)[0]), "+f"((c)[1]), "+f"((c)[2]), "+f"((c)[3]) \
        : "r"((a)[0]), "r"((a)[1]), "r"((a)[2]), "r"((a)[3]), "r"(b0v), "r"(b1v))
#define CPASYNC16(dst, src) \
    asm volatile("cp.async.cg.shared.global [%0], [%1], 16;" :: "r"(dst), "l"(src))
#define CPCOMMIT() asm volatile("cp.async.commit_group;" ::: "memory")
#define CPWAIT0()  asm volatile("cp.async.wait_group 0;" ::: "memory")

// ---------------- kernel 1: perturb + normalize + fp16 ----------------
__global__ void prep_kernel(const int* __restrict__ utt, const float* __restrict__ emb,
                            const float* __restrict__ grad) {
    const int t = blockIdx.x, tid = threadIdx.x;  // 128 threads
    const int token = utt[t];
    float4 e = *(const float4*)(emb + (size_t)token * D_ + tid * 4);
    float4 g = *(const float4*)(grad + (size_t)t * D_ + tid * 4);
    float p0 = e.x + 0.4f * ((g.x > 0.f) ? 1.f : ((g.x < 0.f) ? -1.f : 0.f));
    float p1 = e.y + 0.4f * ((g.y > 0.f) ? 1.f : ((g.y < 0.f) ? -1.f : 0.f));
    float p2 = e.z + 0.4f * ((g.z > 0.f) ? 1.f : ((g.z < 0.f) ? -1.f : 0.f));
    float p3 = e.w + 0.4f * ((g.w > 0.f) ? 1.f : ((g.w < 0.f) ? -1.f : 0.f));
    float ss = p0*p0 + p1*p1 + p2*p2 + p3*p3;
#pragma unroll
    for (int off = 16; off; off >>= 1) ss += __shfl_xor_sync(0xffffffffu, ss, off);
    __shared__ float wsum[4];
    if ((tid & 31) == 0) wsum[tid >> 5] = ss;
    __syncthreads();
    float inv = 1.f / fmaxf(sqrtf(wsum[0] + wsum[1] + wsum[2] + wsum[3]), 1e-8f);
    p0 *= inv; p1 *= inv; p2 *= inv; p3 *= inv;
    g_pnh2[t * 128 + tid] = make_uint2(f16x2_of(p0, p1), f16x2_of(p2, p3));
}

// ---------------- kernel 2: emb -> fp16 + inverse norms (one pass) ----------------
__global__ void conv_kernel(const float* __restrict__ emb) {
    const int row = blockIdx.x * 8 + (threadIdx.x >> 5);   // 256 threads, 8 rows/block
    const int lane = threadIdx.x & 31;
    if (row >= V_) return;
    const float4* src = (const float4*)(emb + (size_t)row * D_ + lane * 16);
    float4 a = src[0], b = src[1], c = src[2], d = src[3];
    float ss = a.x*a.x + a.y*a.y + a.z*a.z + a.w*a.w
             + b.x*b.x + b.y*b.y + b.z*b.z + b.w*b.w
             + c.x*c.x + c.y*c.y + c.z*c.z + c.w*c.w
             + d.x*d.x + d.y*d.y + d.z*d.z + d.w*d.w;
    uint4 o0, o1;
    o0.x = f16x2_of(a.x, a.y); o0.y = f16x2_of(a.z, a.w);
    o0.z = f16x2_of(b.x, b.y); o0.w = f16x2_of(b.z, b.w);
    o1.x = f16x2_of(c.x, c.y); o1.y = f16x2_of(c.z, c.w);
    o1.z = f16x2_of(d.x, d.y); o1.w = f16x2_of(d.z, d.w);
    uint4* dst = (uint4*)((char*)g_embh + (size_t)row * 1024 + lane * 32);
    dst[0] = o0; dst[1] = o1;
#pragma unroll
    for (int off = 16; off; off >>= 1) ss += __shfl_xor_sync(0xffffffffu, ss, off);
    if (lane == 0) g_inv_enorm[row] = 1.f / fmaxf(sqrtf(ss), 1e-8f);
}

// ---------------- kernel 3: pure fp16 GEMM (cp.async both tiles) + fused argmax ----
__global__ void __launch_bounds__(512, 2) gemm_kernel(float* __restrict__ simout,
                                                      const float* __restrict__ noise) {
    extern __shared__ char smem[];
    const uint32_t sb = smem_u32(smem);
    const int tid = threadIdx.x;
    const int wid = tid >> 5, lane = tid & 31;
    const int tblk = blockIdx.x * BN;
    const int vblk = blockIdx.y * BM;

    // smem: A bufs @0,16384 ; B bufs @32768,49152 ; sInv @65536 (512B)
    float acc[2][4][4];
#pragma unroll
    for (int i = 0; i < 2; i++)
#pragma unroll
        for (int j = 0; j < 4; j++)
#pragma unroll
            for (int q = 0; q < 4; q++) acc[i][j][q] = 0.f;

    const int mw = (wid >> 2) * 32;
    const int nw = (wid & 3) * 32;
    const int a_row = (lane & 7) + ((lane >> 3) & 1) * 8;
    const int a_kb  = ((lane >> 4) & 1) * 16;
    const int b_row = (lane & 7) + ((lane >> 4) & 1) * 8;
    const int b_kb  = ((lane >> 3) & 1) * 16;

    // load coords: 1024 16B-segments per tile, 2 per thread
    const int lrow = tid >> 3;          // 0..63  (+64 for second op)
    const int lseg = tid & 7;

    // ---- preamble: issue chunk 0 into buf 0 ----
#pragma unroll
    for (int r = 0; r < 2; r++) {
        int row = lrow + 64 * r;
        uint32_t soff = SW128((uint32_t)(row * 128 + lseg * 16));
        CPASYNC16(sb + soff,
                  (const char*)g_embh + (size_t)(vblk + row) * 1024 + lseg * 16);
        CPASYNC16(sb + 32768 + soff,
                  (const char*)g_pnh2 + (size_t)(tblk + row) * 1024 + lseg * 16);
    }
    CPCOMMIT();

    for (int c = 0; c < NCH; c++) {
        const int bb = c & 1;
        CPWAIT0();
        __syncthreads();                 // chunk c ready; compute(c-1) done
        if (c < NCH - 1) {
            const uint32_t nb = (uint32_t)((bb ^ 1) * 16384);
            const size_t kbyte = (size_t)(c + 1) * 128;
#pragma unroll
            for (int r = 0; r < 2; r++) {
                int row = lrow + 64 * r;
                uint32_t soff = SW128((uint32_t)(row * 128 + lseg * 16));
                CPASYNC16(sb + nb + soff,
                          (const char*)g_embh + (size_t)(vblk + row) * 1024 + kbyte + lseg * 16);
                CPASYNC16(sb + 32768 + nb + soff,
                          (const char*)g_pnh2 + (size_t)(tblk + row) * 1024 + kbyte + lseg * 16);
            }
            CPCOMMIT();
        }
        const uint32_t AB = (uint32_t)(bb * 16384), BB = 32768 + (uint32_t)(bb * 16384);
#pragma unroll
        for (int s = 0; s < 4; s++) {
            const uint32_t akoff = (uint32_t)(s * 32 + a_kb);
            const uint32_t bkoff = (uint32_t)(s * 32 + b_kb);
            uint32_t ah[8], bh[8];
#pragma unroll
            for (int i = 0; i < 2; i++)
                ldsm4(&ah[i*4], sb + AB + SW128((uint32_t)((mw + i*16 + a_row) * 128) + akoff));
#pragma unroll
            for (int j2 = 0; j2 < 2; j2++)
                ldsm4(&bh[j2*4], sb + BB + SW128((uint32_t)((nw + j2*16 + b_row) * 128) + bkoff));
#pragma unroll
            for (int i = 0; i < 2; i++)
#pragma unroll
                for (int j = 0; j < 4; j++)
                    MMA16816(acc[i][j], &ah[i*4], bh[(j>>1)*4 + (j&1)*2], bh[(j>>1)*4 + (j&1)*2 + 1]);
        }
    }
    __syncthreads();

    // ---- load inv norms into smem ----
    float* sInv = (float*)(smem + 65536);
    if (tid < 128) sInv[tid] = g_inv_enorm[vblk + tid];
    __syncthreads();

    // ---- epilogue: stage 64 tokens/phase through smem, fused argmax ----
    float* cs = (float*)smem;              // [64][132] floats = 33792 B (A/B bufs dead)
    const int v4 = lane * 4;
    for (int p = 0; p < 2; p++) {
        __syncthreads();
        if ((nw & 64) == p * 64) {
#pragma unroll
            for (int i = 0; i < 2; i++)
#pragma unroll
                for (int j = 0; j < 4; j++) {
                    int v0 = mw + i * 16 + (lane >> 2);
                    int tl = (nw & 32) + j * 8 + (lane & 3) * 2;
                    cs[ tl      * 132 + v0    ] = acc[i][j][0];
                    cs[(tl + 1) * 132 + v0    ] = acc[i][j][1];
                    cs[ tl      * 132 + v0 + 8] = acc[i][j][2];
                    cs[(tl + 1) * 132 + v0 + 8] = acc[i][j][3];
                }
        }
        __syncthreads();
#pragma unroll
        for (int it = 0; it < 4; it++) {
            int tl = (tid >> 5) + it * 16;
            int gt = tblk + p * 64 + tl;
            float4 val = *(float4*)(cs + tl * 132 + v4);
            val.x *= sInv[v4];
            val.y *= sInv[v4 + 1];
            val.z *= sInv[v4 + 2];
            val.w *= sInv[v4 + 3];
            int gv = vblk + v4;
            // scalar stores: sim row base gt*V_ only 4B aligned (V_ odd)
            float* dst = simout + (size_t)gt * V_ + gv;
            if (gv     < V_) dst[0] = val.x;
            if (gv + 1 < V_) dst[1] = val.y;
            if (gv + 2 < V_) dst[2] = val.z;
            if (gv + 3 < V_) dst[3] = val.w;
            // fused partial argmax over this CTA's 128 v for token gt
            const float* nrow = noise + (size_t)gt * V_;
            float fs = -3e38f; int fv = 0;
            float e[4] = {val.x, val.y, val.z, val.w};
#pragma unroll
            for (int u = 0; u < 4; u++) {
                float sv = (gv + u < V_) ? e[u] : -3e38f;
                if (sv > fs) { fs = sv; fv = gv + u; }
                else if (sv == fs && sv > -3e38f) {
                    float n1 = nrow[fv], n2 = nrow[gv + u];
                    if (n2 > n1) fv = gv + u;
                }
            }
#pragma unroll
            for (int off = 16; off; off >>= 1) {
                float os = __shfl_xor_sync(0xffffffffu, fs, off);
                int   ov = __shfl_xor_sync(0xffffffffu, fv, off);
                bool take = os > fs;
                if (!take && os == fs && os > -3e38f) {
                    float n1 = nrow[fv], n2 = nrow[ov];
                    take = (n2 > n1) || (n2 == n1 && ov < fv);
                }
                if (take) { fs = os; fv = ov; }
            }
            if (lane == 0) {
                g_part_s[gt * NVB + blockIdx.y] = fs;
                g_part_i[gt * NVB + blockIdx.y] = fv;
            }
        }
    }
}

// ---------------- kernel 4: merge partials ----------------
__global__ void merge_kernel(const float* __restrict__ noise,
                             void* __restrict__ out, int write_float) {
    const int t = blockIdx.x, tid = threadIdx.x;   // 128 threads
    const float* ps = g_part_s + t * NVB;
    const int*   pi = g_part_i + t * NVB;

    float s = -3e38f;
    for (int j = tid; j < NVB; j += 128) s = fmaxf(s, ps[j]);
#pragma unroll
    for (int off = 16; off; off >>= 1) s = fmaxf(s, __shfl_xor_sync(0xffffffffu, s, off));
    __shared__ float sm[4];
    if ((tid & 31) == 0) sm[tid >> 5] = s;
    __syncthreads();
    float smax = fmaxf(fmaxf(sm[0], sm[1]), fmaxf(sm[2], sm[3]));

    const float* nrow = noise + (size_t)t * V_;
    float bn = -2.f; int bv = 0x7fffffff;
    for (int j = tid; j < NVB; j += 128) {
        if (ps[j] == smax) {
            int v = pi[j];
            float n = nrow[v];
            if (n > bn || (n == bn && v < bv)) { bn = n; bv = v; }
        }
    }
#pragma unroll
    for (int off = 16; off; off >>= 1) {
        float on = __shfl_xor_sync(0xffffffffu, bn, off);
        int   ov = __shfl_xor_sync(0xffffffffu, bv, off);
        if (on > bn || (on == bn && ov < bv)) { bn = on; bv = ov; }
    }
    __shared__ float nm[4]; __shared__ int vm[4];
    if ((tid & 31) == 0) { nm[tid >> 5] = bn; vm[tid >> 5] = bv; }
    __syncthreads();
    if (tid == 0) {
#pragma unroll
        for (int w = 1; w < 4; w++) {
            if (nm[w] > nm[0] || (nm[w] == nm[0] && vm[w] < vm[0])) { nm[0] = nm[w]; vm[0] = vm[w]; }
        }
        if (write_float) ((float*)out)[t] = (float)vm[0];
        else             ((int*)out)[t]   = vm[0];
    }
}

// ---------------- launcher ----------------
extern "C" void kernel_launch(void* const* d_in, const int* in_sizes, int n_in,
                              void* d_out, int out_size) {
    const int*   utt   = (const int*)d_in[0];
    const float* emb   = (const float*)d_in[1];
    const float* grad  = (const float*)d_in[2];
    const float* noise = (const float*)d_in[3];

    prep_kernel<<<BS_, 128>>>(utt, emb, grad);
    conv_kernel<<<(V_ + 7) / 8, 256>>>(emb);

    const long long SIMN = (long long)BS_ * V_;
    float* simptr;
    float* simscr;
    cudaGetSymbolAddress((void**)&simscr, g_sim_scratch);
    if ((long long)out_size == SIMN + BS_)      simptr = (float*)d_out + BS_;
    else if ((long long)out_size == SIMN)       simptr = (float*)d_out;
    else                                        simptr = simscr;

    cudaFuncSetAttribute(gemm_kernel, cudaFuncAttributeMaxDynamicSharedMemorySize, 66048);
    dim3 grid(BS_ / BN, NVB);
    gemm_kernel<<<grid, 512, 66048>>>(simptr, noise);

    if ((long long)out_size == SIMN + BS_)
        merge_kernel<<<BS_, 128>>>(noise, d_out, 1);
    else if (out_size == BS_)
        merge_kernel<<<BS_, 128>>>(noise, d_out, 0);
}